// round 4
// baseline (speedup 1.0000x reference)
#include <cuda_runtime.h>
#include <cstdint>
#include <math.h>

#define T_    4096
#define H_    2048
#define I_    1408
#define E_    8
#define TWOI  2816
#define TILE_T 8

// Scratch (no allocations allowed -> __device__ globals)
__device__ int8_t g_qin[(size_t)T_ * H_];          // 8 MB  quantized hidden
__device__ float  g_sin[T_];                       // per-token input scale
__device__ int    g_cnt[E_];                       // tokens per expert
__device__ int    g_tok[E_][T_];                   // packed t*2+slot
__device__ float  g_gate[E_][T_];                  // gate value per entry
__device__ float  g_partial[(size_t)T_ * 2 * H_];  // 64 MB (T,K,H) partials
__device__ int8_t g_w13[(size_t)E_ * TWOI * H_];   // 44 MB normalized int8 w13
__device__ int8_t g_w2[(size_t)E_ * H_ * I_];      // 22 MB normalized int8 w2
__device__ int    g_mode;                          // 0=int8 raw, 1=int32, 2=float32

__global__ void reset_kernel() {
    if (threadIdx.x < E_) g_cnt[threadIdx.x] = 0;
}

// ---------------------------------------------------------------------------
// Detect how the harness uploaded the int8 weight tensors.
// ---------------------------------------------------------------------------
__global__ void detect_kernel(const void* __restrict__ w13raw) {
    if (threadIdx.x != 0 || blockIdx.x != 0) return;
    int ok32 = 0, okf = 0;
    const int* as_i = (const int*)w13raw;
    const float* as_f = (const float*)w13raw;
    for (int i = 0; i < 256; ++i) {
        int v = as_i[i];
        if (v >= -127 && v <= 127) ok32++;
        float f = as_f[i];
        if (fabsf(f) <= 127.f && rintf(f) == f) okf++;
    }
    g_mode = (ok32 >= 250) ? 1 : ((okf >= 250) ? 2 : 0);
}

// Normalize weight tensors into int8 scratch. Destinations are referenced
// from DEVICE code (passing a __device__ symbol as a host-side kernel arg
// is invalid -- that was the Round-2/3 fault).
__device__ __forceinline__ char4 conv_elem(const void* __restrict__ src, int idx, int mode) {
    if (mode == 1) {
        int4 v = ((const int4*)src)[idx];
        return make_char4((signed char)v.x, (signed char)v.y, (signed char)v.z, (signed char)v.w);
    } else if (mode == 2) {
        float4 v = ((const float4*)src)[idx];
        return make_char4((signed char)(int)v.x, (signed char)(int)v.y,
                          (signed char)(int)v.z, (signed char)(int)v.w);
    }
    return ((const char4*)src)[idx];
}

#define N4_W13 ((E_ * TWOI * H_) / 4)   // 11534336
#define N4_W2  ((E_ * H_ * I_) / 4)     // 5767168

__global__ __launch_bounds__(256) void convert_w13_kernel(const void* __restrict__ src) {
    int mode = g_mode;
    for (int idx = blockIdx.x * 256 + threadIdx.x; idx < N4_W13; idx += gridDim.x * 256)
        ((char4*)g_w13)[idx] = conv_elem(src, idx, mode);
}

__global__ __launch_bounds__(256) void convert_w2_kernel(const void* __restrict__ src) {
    int mode = g_mode;
    for (int idx = blockIdx.x * 256 + threadIdx.x; idx < N4_W2; idx += gridDim.x * 256)
        ((char4*)g_w2)[idx] = conv_elem(src, idx, mode);
}

// ---------------------------------------------------------------------------
// Gating: logits = x @ gw^T, softmax->top2->gates, absmax -> s_in, scatter
// ---------------------------------------------------------------------------
__global__ __launch_bounds__(256) void gate_kernel(const float* __restrict__ hid,
                                                   const float* __restrict__ gw) {
    int t = blockIdx.x;
    const float* x = hid + (size_t)t * H_;
    float part[E_];
#pragma unroll
    for (int e = 0; e < E_; ++e) part[e] = 0.f;
    float amax = 0.f;
    for (int j = threadIdx.x; j < H_; j += 256) {
        float v = x[j];
        amax = fmaxf(amax, fabsf(v));
#pragma unroll
        for (int e = 0; e < E_; ++e) part[e] = fmaf(v, gw[e * H_ + j], part[e]);
    }
#pragma unroll
    for (int off = 16; off; off >>= 1) {
        amax = fmaxf(amax, __shfl_down_sync(0xffffffffu, amax, off));
#pragma unroll
        for (int e = 0; e < E_; ++e) part[e] += __shfl_down_sync(0xffffffffu, part[e], off);
    }
    __shared__ float red[8][E_ + 1];
    int warp = threadIdx.x >> 5, lane = threadIdx.x & 31;
    if (lane == 0) {
#pragma unroll
        for (int e = 0; e < E_; ++e) red[warp][e] = part[e];
        red[warp][E_] = amax;
    }
    __syncthreads();
    if (threadIdx.x == 0) {
        float l[E_];
        float am = 0.f;
#pragma unroll
        for (int e = 0; e < E_; ++e) l[e] = 0.f;
        for (int w = 0; w < 8; ++w) {
#pragma unroll
            for (int e = 0; e < E_; ++e) l[e] += red[w][e];
            am = fmaxf(am, red[w][E_]);
        }
        // top-2 with first-occurrence-wins tie behavior (strict >)
        float b1 = -1e30f, b2 = -1e30f;
        int i1 = 0, i2 = 0;
#pragma unroll
        for (int e = 0; e < E_; ++e) {
            float v = l[e];
            if (v > b1) { b2 = b1; i2 = i1; b1 = v; i1 = e; }
            else if (v > b2) { b2 = v; i2 = e; }
        }
        // gates = softmax top2 renormalized -> exp ratio
        float e2v = expf(b2 - b1);
        float inv = __fdiv_rn(1.f, 1.f + e2v);
        float g0 = inv;
        float g1 = e2v * inv;

        g_sin[t] = fmaxf(__fdiv_rn(am, 127.f), 1e-8f);

        int p0 = atomicAdd(&g_cnt[i1], 1);
        g_tok[i1][p0] = t * 2 + 0;
        g_gate[i1][p0] = g0;
        int p1 = atomicAdd(&g_cnt[i2], 1);
        g_tok[i2][p1] = t * 2 + 1;
        g_gate[i2][p1] = g1;
    }
}

// ---------------------------------------------------------------------------
// Quantize hidden to int8 with per-token scale (round half-to-even = rintf)
// ---------------------------------------------------------------------------
__global__ __launch_bounds__(256) void quant_kernel(const float* __restrict__ hid) {
    int t = blockIdx.x;
    float s = g_sin[t];
    const float4* x = (const float4*)(hid + (size_t)t * H_);
    char4* q = (char4*)(g_qin + (size_t)t * H_);
    for (int j = threadIdx.x; j < H_ / 4; j += 256) {
        float4 v = x[j];
        float a = fminf(fmaxf(rintf(__fdiv_rn(v.x, s)), -127.f), 127.f);
        float b = fminf(fmaxf(rintf(__fdiv_rn(v.y, s)), -127.f), 127.f);
        float c = fminf(fmaxf(rintf(__fdiv_rn(v.z, s)), -127.f), 127.f);
        float d = fminf(fmaxf(rintf(__fdiv_rn(v.w, s)), -127.f), 127.f);
        q[j] = make_char4((signed char)a, (signed char)b, (signed char)c, (signed char)d);
    }
}

// ---------------------------------------------------------------------------
// Fused expert: GEMM1(dp4a) -> silu*up -> requant -> GEMM2(dp4a) -> partial
// grid = (T/TILE_T, E), 256 threads, ~73KB dynamic smem
// ---------------------------------------------------------------------------
#define SMEM_Q    (TILE_T * H_)                 // 16384 int8
#define SMEM_ACT  (TILE_T * I_ * 4)             // 45056 float bytes
#define SMEM_QACT (TILE_T * I_)                 // 11264 int8
#define SMEM_META 128
#define SMEM_BYTES (SMEM_Q + SMEM_ACT + SMEM_QACT + SMEM_META)  // 72832

__global__ __launch_bounds__(256) void expert_kernel(
    const float* __restrict__ s13_all, const float* __restrict__ s2_all) {
    int e = blockIdx.y;
    int cnt = g_cnt[e];
    int base = blockIdx.x * TILE_T;
    if (base >= cnt) return;
    int nt = min(TILE_T, cnt - base);

    extern __shared__ char smem[];
    int8_t* q_tile = (int8_t*)smem;
    float* act = (float*)(smem + SMEM_Q);
    int8_t* qact = (int8_t*)(smem + SMEM_Q + SMEM_ACT);
    float* meta = (float*)(smem + SMEM_Q + SMEM_ACT + SMEM_QACT);
    float* sin_s = meta;          // [0..7]
    float* gate_s = meta + 8;     // [8..15]
    float* sa_s = meta + 16;      // [16..23]
    int* dst_s = (int*)(meta + 24);

    const int8_t* w13 = g_w13 + (size_t)e * TWOI * H_;
    const float* s13 = s13_all + (size_t)e * TWOI;
    const int8_t* w2 = g_w2 + (size_t)e * H_ * I_;
    const float* s2w = s2_all + (size_t)e * H_;

    int tid = threadIdx.x;
    if (tid < TILE_T) {
        int packed;
        if (tid < nt) {
            packed = g_tok[e][base + tid];
            gate_s[tid] = g_gate[e][base + tid];
        } else {
            packed = g_tok[e][base];   // duplicate a valid token; never stored
            gate_s[tid] = 0.f;
        }
        dst_s[tid] = packed;
        sin_s[tid] = g_sin[packed >> 1];
    }
    __syncthreads();

    // Stage q_in rows (gather) into smem, vectorized
    for (int idx = tid; idx < TILE_T * (H_ / 16); idx += 256) {
        int tt = idx >> 7;          // H_/16 == 128
        int kk = idx & 127;
        int trow = dst_s[tt] >> 1;
        ((int4*)(q_tile + tt * H_))[kk] = ((const int4*)(g_qin + (size_t)trow * H_))[kk];
    }
    __syncthreads();

    // GEMM1 (gate+up columns together) + SiLU*up
    for (int i = tid; i < I_; i += 256) {
        int accg[TILE_T], accu[TILE_T];
#pragma unroll
        for (int tt = 0; tt < TILE_T; ++tt) { accg[tt] = 0; accu[tt] = 0; }
        const int4* wg = (const int4*)(w13 + (size_t)i * H_);
        const int4* wu = (const int4*)(w13 + (size_t)(i + I_) * H_);
        for (int kk = 0; kk < H_ / 16; ++kk) {
            int4 wgv = wg[kk];
            int4 wuv = wu[kk];
#pragma unroll
            for (int tt = 0; tt < TILE_T; ++tt) {
                int4 av = ((const int4*)(q_tile + tt * H_))[kk];
                accg[tt] = __dp4a(av.x, wgv.x, accg[tt]);
                accg[tt] = __dp4a(av.y, wgv.y, accg[tt]);
                accg[tt] = __dp4a(av.z, wgv.z, accg[tt]);
                accg[tt] = __dp4a(av.w, wgv.w, accg[tt]);
                accu[tt] = __dp4a(av.x, wuv.x, accu[tt]);
                accu[tt] = __dp4a(av.y, wuv.y, accu[tt]);
                accu[tt] = __dp4a(av.z, wuv.z, accu[tt]);
                accu[tt] = __dp4a(av.w, wuv.w, accu[tt]);
            }
        }
        float sg = s13[i];
        float su = s13[i + I_];
#pragma unroll
        for (int tt = 0; tt < TILE_T; ++tt) {
            float si = sin_s[tt];
            float g = (float)accg[tt] * si * sg;
            float u = (float)accu[tt] * si * su;
            float sig = __fdiv_rn(1.f, 1.f + expf(-g));
            act[tt * I_ + i] = g * sig * u;
        }
    }
    __syncthreads();

    // Per-token absmax -> activation scale (one warp per token; 8 warps)
    {
        int w = tid >> 5, lane = tid & 31;
        float m = 0.f;
        for (int i = lane; i < I_; i += 32) m = fmaxf(m, fabsf(act[w * I_ + i]));
#pragma unroll
        for (int off = 16; off; off >>= 1)
            m = fmaxf(m, __shfl_down_sync(0xffffffffu, m, off));
        if (lane == 0) sa_s[w] = fmaxf(__fdiv_rn(m, 127.f), 1e-8f);
    }
    __syncthreads();

    // Requantize activations
    for (int idx = tid; idx < TILE_T * I_; idx += 256) {
        int tt = idx / I_;
        float q = fminf(fmaxf(rintf(__fdiv_rn(act[idx], sa_s[tt])), -127.f), 127.f);
        qact[idx] = (int8_t)q;
    }
    __syncthreads();

    // GEMM2 -> scaled partial write
    for (int hc = tid; hc < H_; hc += 256) {
        int acc[TILE_T];
#pragma unroll
        for (int tt = 0; tt < TILE_T; ++tt) acc[tt] = 0;
        const int4* w = (const int4*)(w2 + (size_t)hc * I_);
        for (int kk = 0; kk < I_ / 16; ++kk) {
            int4 wv = w[kk];
#pragma unroll
            for (int tt = 0; tt < TILE_T; ++tt) {
                int4 av = ((const int4*)(qact + tt * I_))[kk];
                acc[tt] = __dp4a(av.x, wv.x, acc[tt]);
                acc[tt] = __dp4a(av.y, wv.y, acc[tt]);
                acc[tt] = __dp4a(av.z, wv.z, acc[tt]);
                acc[tt] = __dp4a(av.w, wv.w, acc[tt]);
            }
        }
        float s2 = s2w[hc];
#pragma unroll
        for (int tt = 0; tt < TILE_T; ++tt) {
            if (tt < nt) {
                float h2 = (float)acc[tt] * sa_s[tt] * s2;
                g_partial[(size_t)dst_s[tt] * H_ + hc] = gate_s[tt] * h2;
            }
        }
    }
}

// ---------------------------------------------------------------------------
// out[t][h] = partial[t][0][h] + partial[t][1][h]
// ---------------------------------------------------------------------------
__global__ __launch_bounds__(256) void finalize_kernel(float* __restrict__ out) {
    size_t idx = (size_t)blockIdx.x * 256 + threadIdx.x;
    size_t t = idx >> 11;          // H_ == 2048
    size_t h = idx & 2047;
    out[idx] = g_partial[(t * 2) * H_ + h] + g_partial[(t * 2 + 1) * H_ + h];
}

extern "C" void kernel_launch(void* const* d_in, const int* in_sizes, int n_in,
                              void* d_out, int out_size) {
    // ---- Robust input resolution -----------------------------------------
    // Accept in_sizes as either ELEMENT counts or BYTE counts, under int8 or
    // widened (int32/float32) weight uploads. Positional fallback = dict order.
    const float* hid = nullptr;   // 8388608 el  / 33554432 B
    const float* gw = nullptr;    // 16384 el    / 65536 B   (first of pair)
    const void* w13raw = nullptr; // 46137344 el / 184549376 B widened
    const float* s13 = nullptr;   // 22528 el    / 90112 B
    const void* w2raw = nullptr;  // 23068672 el / 92274688 B widened
    const float* s2 = nullptr;    // 16384 el    / 65536 B   (second of pair)
    for (int i = 0; i < n_in; ++i) {
        long long s = in_sizes[i];
        if (s == 8388608LL || s == 33554432LL) hid = (const float*)d_in[i];
        else if (s == 46137344LL || s == 184549376LL) w13raw = d_in[i];
        else if (s == 22528LL || s == 90112LL) s13 = (const float*)d_in[i];
        else if (s == 23068672LL || s == 92274688LL) w2raw = d_in[i];
        else if (s == 16384LL || s == 65536LL) {
            if (!gw) gw = (const float*)d_in[i];
            else s2 = (const float*)d_in[i];
        }
    }
    if (n_in >= 6) {
        if (!hid)    hid = (const float*)d_in[0];
        if (!gw)     gw = (const float*)d_in[1];
        if (!w13raw) w13raw = d_in[2];
        if (!s13)    s13 = (const float*)d_in[3];
        if (!w2raw)  w2raw = d_in[4];
        if (!s2)     s2 = (const float*)d_in[5];
    }
    float* out = (float*)d_out;

    cudaFuncSetAttribute(expert_kernel, cudaFuncAttributeMaxDynamicSharedMemorySize,
                         SMEM_BYTES);

    reset_kernel<<<1, 32>>>();
    detect_kernel<<<1, 32>>>(w13raw);
    convert_w13_kernel<<<8192, 256>>>(w13raw);
    convert_w2_kernel<<<8192, 256>>>(w2raw);
    gate_kernel<<<T_, 256>>>(hid, gw);
    quant_kernel<<<T_, 256>>>(hid);
    dim3 egrid(T_ / TILE_T, E_);
    expert_kernel<<<egrid, 256, SMEM_BYTES>>>(s13, s2);
    finalize_kernel<<<(T_ * H_) / 256, 256>>>(out);
}

// round 5
// speedup vs baseline: 2.0073x; 2.0073x over previous
#include <cuda_runtime.h>
#include <cstdint>
#include <math.h>

#define T_    4096
#define H_    2048
#define I_    1408
#define E_    8
#define TWOI  2816
#define TILE_T 16
#define NTHR  512

// Scratch (no allocations allowed -> __device__ globals)
__device__ int8_t g_qin[(size_t)T_ * H_];          // 8 MB  quantized hidden
__device__ float  g_sin[T_];                       // per-token input scale
__device__ int    g_cnt[E_];                       // tokens per expert
__device__ int    g_tok[E_][T_];                   // packed t*2+slot
__device__ float  g_gate[E_][T_];                  // gate value per entry
__device__ float  g_partial[(size_t)T_ * 2 * H_];  // 64 MB (T,K,H) partials
__device__ int8_t g_w13[(size_t)E_ * TWOI * H_];   // 44 MB normalized int8 w13
__device__ int8_t g_w2[(size_t)E_ * H_ * I_];      // 22 MB normalized int8 w2
__device__ int    g_mode;                          // 0=int8 raw, 1=int32, 2=float32

// ---------------------------------------------------------------------------
// Init: zero expert counters + detect weight upload dtype (merged so that
// expert_kernel is launch #6 -> fixed ncu -s 5 -c 1 profiles the hot kernel)
// ---------------------------------------------------------------------------
__global__ void init_kernel(const void* __restrict__ w13raw) {
    if (threadIdx.x < E_) g_cnt[threadIdx.x] = 0;
    if (threadIdx.x != 0) return;
    int ok32 = 0, okf = 0;
    const int* as_i = (const int*)w13raw;
    const float* as_f = (const float*)w13raw;
    for (int i = 0; i < 256; ++i) {
        int v = as_i[i];
        if (v >= -127 && v <= 127) ok32++;
        float f = as_f[i];
        if (fabsf(f) <= 127.f && rintf(f) == f) okf++;
    }
    g_mode = (ok32 >= 250) ? 1 : ((okf >= 250) ? 2 : 0);
}

// Normalize weight tensors into int8 scratch (device-side symbol refs only).
__device__ __forceinline__ char4 conv_elem(const void* __restrict__ src, int idx, int mode) {
    if (mode == 1) {
        int4 v = ((const int4*)src)[idx];
        return make_char4((signed char)v.x, (signed char)v.y, (signed char)v.z, (signed char)v.w);
    } else if (mode == 2) {
        float4 v = ((const float4*)src)[idx];
        return make_char4((signed char)(int)v.x, (signed char)(int)v.y,
                          (signed char)(int)v.z, (signed char)(int)v.w);
    }
    return ((const char4*)src)[idx];
}

#define N4_W13 ((E_ * TWOI * H_) / 4)   // 11534336
#define N4_W2  ((E_ * H_ * I_) / 4)     // 5767168

__global__ __launch_bounds__(256) void convert_w13_kernel(const void* __restrict__ src) {
    int mode = g_mode;
    for (int idx = blockIdx.x * 256 + threadIdx.x; idx < N4_W13; idx += gridDim.x * 256)
        ((char4*)g_w13)[idx] = conv_elem(src, idx, mode);
}

__global__ __launch_bounds__(256) void convert_w2_kernel(const void* __restrict__ src) {
    int mode = g_mode;
    for (int idx = blockIdx.x * 256 + threadIdx.x; idx < N4_W2; idx += gridDim.x * 256)
        ((char4*)g_w2)[idx] = conv_elem(src, idx, mode);
}

// ---------------------------------------------------------------------------
// Gating: logits = x @ gw^T, softmax->top2->gates, absmax -> s_in, scatter
// ---------------------------------------------------------------------------
__global__ __launch_bounds__(256) void gate_kernel(const float* __restrict__ hid,
                                                   const float* __restrict__ gw) {
    int t = blockIdx.x;
    const float* x = hid + (size_t)t * H_;
    float part[E_];
#pragma unroll
    for (int e = 0; e < E_; ++e) part[e] = 0.f;
    float amax = 0.f;
    for (int j = threadIdx.x; j < H_; j += 256) {
        float v = x[j];
        amax = fmaxf(amax, fabsf(v));
#pragma unroll
        for (int e = 0; e < E_; ++e) part[e] = fmaf(v, gw[e * H_ + j], part[e]);
    }
#pragma unroll
    for (int off = 16; off; off >>= 1) {
        amax = fmaxf(amax, __shfl_down_sync(0xffffffffu, amax, off));
#pragma unroll
        for (int e = 0; e < E_; ++e) part[e] += __shfl_down_sync(0xffffffffu, part[e], off);
    }
    __shared__ float red[8][E_ + 1];
    int warp = threadIdx.x >> 5, lane = threadIdx.x & 31;
    if (lane == 0) {
#pragma unroll
        for (int e = 0; e < E_; ++e) red[warp][e] = part[e];
        red[warp][E_] = amax;
    }
    __syncthreads();
    if (threadIdx.x == 0) {
        float l[E_];
        float am = 0.f;
#pragma unroll
        for (int e = 0; e < E_; ++e) l[e] = 0.f;
        for (int w = 0; w < 8; ++w) {
#pragma unroll
            for (int e = 0; e < E_; ++e) l[e] += red[w][e];
            am = fmaxf(am, red[w][E_]);
        }
        float b1 = -1e30f, b2 = -1e30f;
        int i1 = 0, i2 = 0;
#pragma unroll
        for (int e = 0; e < E_; ++e) {
            float v = l[e];
            if (v > b1) { b2 = b1; i2 = i1; b1 = v; i1 = e; }
            else if (v > b2) { b2 = v; i2 = e; }
        }
        float e2v = expf(b2 - b1);
        float inv = __fdiv_rn(1.f, 1.f + e2v);
        float g0 = inv;
        float g1 = e2v * inv;

        g_sin[t] = fmaxf(__fdiv_rn(am, 127.f), 1e-8f);

        int p0 = atomicAdd(&g_cnt[i1], 1);
        g_tok[i1][p0] = t * 2 + 0;
        g_gate[i1][p0] = g0;
        int p1 = atomicAdd(&g_cnt[i2], 1);
        g_tok[i2][p1] = t * 2 + 1;
        g_gate[i2][p1] = g1;
    }
}

// ---------------------------------------------------------------------------
// Quantize hidden to int8 with per-token scale (round half-to-even = rintf)
// ---------------------------------------------------------------------------
__global__ __launch_bounds__(256) void quant_kernel(const float* __restrict__ hid) {
    int t = blockIdx.x;
    float s = g_sin[t];
    const float4* x = (const float4*)(hid + (size_t)t * H_);
    char4* q = (char4*)(g_qin + (size_t)t * H_);
    for (int j = threadIdx.x; j < H_ / 4; j += 256) {
        float4 v = x[j];
        float a = fminf(fmaxf(rintf(__fdiv_rn(v.x, s)), -127.f), 127.f);
        float b = fminf(fmaxf(rintf(__fdiv_rn(v.y, s)), -127.f), 127.f);
        float c = fminf(fmaxf(rintf(__fdiv_rn(v.z, s)), -127.f), 127.f);
        float d = fminf(fmaxf(rintf(__fdiv_rn(v.w, s)), -127.f), 127.f);
        q[j] = make_char4((signed char)a, (signed char)b, (signed char)c, (signed char)d);
    }
}

// ---------------------------------------------------------------------------
// Fused expert: GEMM1(dp4a) -> silu*up -> requant -> GEMM2(dp4a) -> partial
// grid = (T/TILE_T, E), 512 threads, ~145KB dynamic smem
// ---------------------------------------------------------------------------
#define SMEM_Q    (TILE_T * H_)                 // 32768 int8
#define SMEM_ACT  (TILE_T * I_ * 4)             // 90112 float bytes
#define SMEM_QACT (TILE_T * I_)                 // 22528 int8
#define SMEM_META 256
#define SMEM_BYTES (SMEM_Q + SMEM_ACT + SMEM_QACT + SMEM_META)  // 145664

__global__ __launch_bounds__(NTHR) void expert_kernel(
    const float* __restrict__ s13_all, const float* __restrict__ s2_all) {
    int e = blockIdx.y;
    int cnt = g_cnt[e];
    int base = blockIdx.x * TILE_T;
    if (base >= cnt) return;
    int nt = min(TILE_T, cnt - base);

    extern __shared__ char smem[];
    int8_t* q_tile = (int8_t*)smem;
    float* act = (float*)(smem + SMEM_Q);
    int8_t* qact = (int8_t*)(smem + SMEM_Q + SMEM_ACT);
    float* meta = (float*)(smem + SMEM_Q + SMEM_ACT + SMEM_QACT);
    float* sin_s = meta;           // [0..15]
    float* gate_s = meta + 16;     // [16..31]
    float* sa_s = meta + 32;       // [32..47]
    int* dst_s = (int*)(meta + 48);

    const int8_t* w13 = g_w13 + (size_t)e * TWOI * H_;
    const float* s13 = s13_all + (size_t)e * TWOI;
    const int8_t* w2 = g_w2 + (size_t)e * H_ * I_;
    const float* s2w = s2_all + (size_t)e * H_;

    int tid = threadIdx.x;
    if (tid < TILE_T) {
        int packed;
        if (tid < nt) {
            packed = g_tok[e][base + tid];
            gate_s[tid] = g_gate[e][base + tid];
        } else {
            packed = g_tok[e][base];   // duplicate a valid token; never stored
            gate_s[tid] = 0.f;
        }
        dst_s[tid] = packed;
        sin_s[tid] = g_sin[packed >> 1];
    }
    __syncthreads();

    // Stage q_in rows (gather) into smem, vectorized (int4 = 16B)
    for (int idx = tid; idx < TILE_T * (H_ / 16); idx += NTHR) {
        int tt = idx >> 7;          // H_/16 == 128
        int kk = idx & 127;
        int trow = dst_s[tt] >> 1;
        ((int4*)(q_tile + tt * H_))[kk] = ((const int4*)(g_qin + (size_t)trow * H_))[kk];
    }
    __syncthreads();

    // GEMM1 (gate+up columns together) + SiLU*up
    for (int i = tid; i < I_; i += NTHR) {
        int accg[TILE_T], accu[TILE_T];
#pragma unroll
        for (int tt = 0; tt < TILE_T; ++tt) { accg[tt] = 0; accu[tt] = 0; }
        const int4* wg = (const int4*)(w13 + (size_t)i * H_);
        const int4* wu = (const int4*)(w13 + (size_t)(i + I_) * H_);
        for (int kk = 0; kk < H_ / 16; ++kk) {
            int4 wgv = wg[kk];
            int4 wuv = wu[kk];
#pragma unroll
            for (int tt = 0; tt < TILE_T; ++tt) {
                int4 av = ((const int4*)(q_tile + tt * H_))[kk];
                accg[tt] = __dp4a(av.x, wgv.x, accg[tt]);
                accg[tt] = __dp4a(av.y, wgv.y, accg[tt]);
                accg[tt] = __dp4a(av.z, wgv.z, accg[tt]);
                accg[tt] = __dp4a(av.w, wgv.w, accg[tt]);
                accu[tt] = __dp4a(av.x, wuv.x, accu[tt]);
                accu[tt] = __dp4a(av.y, wuv.y, accu[tt]);
                accu[tt] = __dp4a(av.z, wuv.z, accu[tt]);
                accu[tt] = __dp4a(av.w, wuv.w, accu[tt]);
            }
        }
        float sg = s13[i];
        float su = s13[i + I_];
#pragma unroll
        for (int tt = 0; tt < TILE_T; ++tt) {
            float si = sin_s[tt];
            float g = (float)accg[tt] * si * sg;
            float u = (float)accu[tt] * si * su;
            float sig = __fdiv_rn(1.f, 1.f + expf(-g));
            act[tt * I_ + i] = g * sig * u;
        }
    }
    __syncthreads();

    // Per-token absmax -> activation scale (one warp per token; 16 warps)
    {
        int w = tid >> 5, lane = tid & 31;
        float m = 0.f;
        for (int i = lane; i < I_; i += 32) m = fmaxf(m, fabsf(act[w * I_ + i]));
#pragma unroll
        for (int off = 16; off; off >>= 1)
            m = fmaxf(m, __shfl_down_sync(0xffffffffu, m, off));
        if (lane == 0) sa_s[w] = fmaxf(__fdiv_rn(m, 127.f), 1e-8f);
    }
    __syncthreads();

    // Requantize activations
    for (int idx = tid; idx < TILE_T * I_; idx += NTHR) {
        int tt = idx / I_;
        float q = fminf(fmaxf(rintf(__fdiv_rn(act[idx], sa_s[tt])), -127.f), 127.f);
        qact[idx] = (int8_t)q;
    }
    __syncthreads();

    // GEMM2 -> scaled partial write
    for (int hc = tid; hc < H_; hc += NTHR) {
        int acc[TILE_T];
#pragma unroll
        for (int tt = 0; tt < TILE_T; ++tt) acc[tt] = 0;
        const int4* w = (const int4*)(w2 + (size_t)hc * I_);
        for (int kk = 0; kk < I_ / 16; ++kk) {
            int4 wv = w[kk];
#pragma unroll
            for (int tt = 0; tt < TILE_T; ++tt) {
                int4 av = ((const int4*)(qact + tt * I_))[kk];
                acc[tt] = __dp4a(av.x, wv.x, acc[tt]);
                acc[tt] = __dp4a(av.y, wv.y, acc[tt]);
                acc[tt] = __dp4a(av.z, wv.z, acc[tt]);
                acc[tt] = __dp4a(av.w, wv.w, acc[tt]);
            }
        }
        float s2 = s2w[hc];
#pragma unroll
        for (int tt = 0; tt < TILE_T; ++tt) {
            if (tt < nt) {
                float h2 = (float)acc[tt] * sa_s[tt] * s2;
                g_partial[(size_t)dst_s[tt] * H_ + hc] = gate_s[tt] * h2;
            }
        }
    }
}

// ---------------------------------------------------------------------------
// out[t][h] = partial[t][0][h] + partial[t][1][h]
// ---------------------------------------------------------------------------
__global__ __launch_bounds__(256) void finalize_kernel(float* __restrict__ out) {
    size_t idx = (size_t)blockIdx.x * 256 + threadIdx.x;
    size_t t = idx >> 11;          // H_ == 2048
    size_t h = idx & 2047;
    out[idx] = g_partial[(t * 2) * H_ + h] + g_partial[(t * 2 + 1) * H_ + h];
}

extern "C" void kernel_launch(void* const* d_in, const int* in_sizes, int n_in,
                              void* d_out, int out_size) {
    // ---- Robust input resolution (element OR byte counts; positional fallback)
    const float* hid = nullptr;
    const float* gw = nullptr;
    const void* w13raw = nullptr;
    const float* s13 = nullptr;
    const void* w2raw = nullptr;
    const float* s2 = nullptr;
    for (int i = 0; i < n_in; ++i) {
        long long s = in_sizes[i];
        if (s == 8388608LL || s == 33554432LL) hid = (const float*)d_in[i];
        else if (s == 46137344LL || s == 184549376LL) w13raw = d_in[i];
        else if (s == 22528LL || s == 90112LL) s13 = (const float*)d_in[i];
        else if (s == 23068672LL || s == 92274688LL) w2raw = d_in[i];
        else if (s == 16384LL || s == 65536LL) {
            if (!gw) gw = (const float*)d_in[i];
            else s2 = (const float*)d_in[i];
        }
    }
    if (n_in >= 6) {
        if (!hid)    hid = (const float*)d_in[0];
        if (!gw)     gw = (const float*)d_in[1];
        if (!w13raw) w13raw = d_in[2];
        if (!s13)    s13 = (const float*)d_in[3];
        if (!w2raw)  w2raw = d_in[4];
        if (!s2)     s2 = (const float*)d_in[5];
    }
    float* out = (float*)d_out;

    cudaFuncSetAttribute(expert_kernel, cudaFuncAttributeMaxDynamicSharedMemorySize,
                         SMEM_BYTES);

    init_kernel<<<1, 32>>>(w13raw);                 // launch 1
    convert_w13_kernel<<<8192, 256>>>(w13raw);      // launch 2
    convert_w2_kernel<<<8192, 256>>>(w2raw);        // launch 3
    gate_kernel<<<T_, 256>>>(hid, gw);              // launch 4
    quant_kernel<<<T_, 256>>>(hid);                 // launch 5
    dim3 egrid(T_ / TILE_T, E_);
    expert_kernel<<<egrid, NTHR, SMEM_BYTES>>>(s13, s2);  // launch 6 (ncu -s 5)
    finalize_kernel<<<(T_ * H_) / 256, 256>>>(out); // launch 7
}

// round 6
// speedup vs baseline: 2.1791x; 1.0856x over previous
#include <cuda_runtime.h>
#include <cstdint>
#include <math.h>

#define T_    4096
#define H_    2048
#define I_    1408
#define E_    8
#define TWOI  2816
#define TT    32

// Scratch (no allocations allowed -> __device__ globals)
__device__ int8_t g_qin[(size_t)T_ * H_];          // 8 MB quantized hidden
__device__ float  g_sin[T_];
__device__ int    g_cnt[E_];
__device__ int    g_tok[E_][T_];                   // packed t*2+slot
__device__ float  g_gate_arr[E_][T_];
__device__ float  g_partial[(size_t)T_ * 2 * H_];  // 64 MB
__device__ int8_t g_w13[(size_t)E_ * TWOI * H_];   // 44 MB
__device__ int8_t g_w2[(size_t)E_ * H_ * I_];      // 22 MB
__device__ float  g_act[(size_t)T_ * 2 * I_];      // 45 MB fp32 activations
__device__ int8_t g_qact[(size_t)T_ * 2 * I_];     // 11.5 MB
__device__ float  g_sa[T_ * 2];
__device__ int    g_mode;                          // 0=int8 raw, 1=int32, 2=float32

// ---------------------------------------------------------------------------
__global__ void init_kernel(const void* __restrict__ w13raw) {
    if (threadIdx.x < E_) g_cnt[threadIdx.x] = 0;
    if (threadIdx.x != 0) return;
    int ok32 = 0, okf = 0;
    const int* as_i = (const int*)w13raw;
    const float* as_f = (const float*)w13raw;
    for (int i = 0; i < 256; ++i) {
        int v = as_i[i];
        if (v >= -127 && v <= 127) ok32++;
        float f = as_f[i];
        if (fabsf(f) <= 127.f && rintf(f) == f) okf++;
    }
    g_mode = (ok32 >= 250) ? 1 : ((okf >= 250) ? 2 : 0);
}

__device__ __forceinline__ char4 conv_elem(const void* __restrict__ src, int idx, int mode) {
    if (mode == 1) {
        int4 v = ((const int4*)src)[idx];
        return make_char4((signed char)v.x, (signed char)v.y, (signed char)v.z, (signed char)v.w);
    } else if (mode == 2) {
        float4 v = ((const float4*)src)[idx];
        return make_char4((signed char)(int)v.x, (signed char)(int)v.y,
                          (signed char)(int)v.z, (signed char)(int)v.w);
    }
    return ((const char4*)src)[idx];
}

#define N4_W13 ((E_ * TWOI * H_) / 4)
#define N4_W2  ((E_ * H_ * I_) / 4)

__global__ __launch_bounds__(256) void convert_w13_kernel(const void* __restrict__ src) {
    int mode = g_mode;
    for (int idx = blockIdx.x * 256 + threadIdx.x; idx < N4_W13; idx += gridDim.x * 256)
        ((char4*)g_w13)[idx] = conv_elem(src, idx, mode);
}
__global__ __launch_bounds__(256) void convert_w2_kernel(const void* __restrict__ src) {
    int mode = g_mode;
    for (int idx = blockIdx.x * 256 + threadIdx.x; idx < N4_W2; idx += gridDim.x * 256)
        ((char4*)g_w2)[idx] = conv_elem(src, idx, mode);
}

// ---------------------------------------------------------------------------
__global__ __launch_bounds__(256) void gate_kernel(const float* __restrict__ hid,
                                                   const float* __restrict__ gw) {
    int t = blockIdx.x;
    const float* x = hid + (size_t)t * H_;
    float part[E_];
#pragma unroll
    for (int e = 0; e < E_; ++e) part[e] = 0.f;
    float amax = 0.f;
    for (int j = threadIdx.x; j < H_; j += 256) {
        float v = x[j];
        amax = fmaxf(amax, fabsf(v));
#pragma unroll
        for (int e = 0; e < E_; ++e) part[e] = fmaf(v, gw[e * H_ + j], part[e]);
    }
#pragma unroll
    for (int off = 16; off; off >>= 1) {
        amax = fmaxf(amax, __shfl_down_sync(0xffffffffu, amax, off));
#pragma unroll
        for (int e = 0; e < E_; ++e) part[e] += __shfl_down_sync(0xffffffffu, part[e], off);
    }
    __shared__ float red[8][E_ + 1];
    int warp = threadIdx.x >> 5, lane = threadIdx.x & 31;
    if (lane == 0) {
#pragma unroll
        for (int e = 0; e < E_; ++e) red[warp][e] = part[e];
        red[warp][E_] = amax;
    }
    __syncthreads();
    if (threadIdx.x == 0) {
        float l[E_];
        float am = 0.f;
#pragma unroll
        for (int e = 0; e < E_; ++e) l[e] = 0.f;
        for (int w = 0; w < 8; ++w) {
#pragma unroll
            for (int e = 0; e < E_; ++e) l[e] += red[w][e];
            am = fmaxf(am, red[w][E_]);
        }
        float b1 = -1e30f, b2 = -1e30f;
        int i1 = 0, i2 = 0;
#pragma unroll
        for (int e = 0; e < E_; ++e) {
            float v = l[e];
            if (v > b1) { b2 = b1; i2 = i1; b1 = v; i1 = e; }
            else if (v > b2) { b2 = v; i2 = e; }
        }
        float e2v = expf(b2 - b1);
        float inv = __fdiv_rn(1.f, 1.f + e2v);
        g_sin[t] = fmaxf(__fdiv_rn(am, 127.f), 1e-8f);
        int p0 = atomicAdd(&g_cnt[i1], 1);
        g_tok[i1][p0] = t * 2 + 0;
        g_gate_arr[i1][p0] = inv;
        int p1 = atomicAdd(&g_cnt[i2], 1);
        g_tok[i2][p1] = t * 2 + 1;
        g_gate_arr[i2][p1] = e2v * inv;
    }
}

__global__ __launch_bounds__(256) void quant_kernel(const float* __restrict__ hid) {
    int t = blockIdx.x;
    float s = g_sin[t];
    const float4* x = (const float4*)(hid + (size_t)t * H_);
    char4* q = (char4*)(g_qin + (size_t)t * H_);
    for (int j = threadIdx.x; j < H_ / 4; j += 256) {
        float4 v = x[j];
        float a = fminf(fmaxf(rintf(__fdiv_rn(v.x, s)), -127.f), 127.f);
        float b = fminf(fmaxf(rintf(__fdiv_rn(v.y, s)), -127.f), 127.f);
        float c = fminf(fmaxf(rintf(__fdiv_rn(v.z, s)), -127.f), 127.f);
        float d = fminf(fmaxf(rintf(__fdiv_rn(v.w, s)), -127.f), 127.f);
        q[j] = make_char4((signed char)a, (signed char)b, (signed char)c, (signed char)d);
    }
}

// ---------------------------------------------------------------------------
// IMMA m16n8k32 s8.s8 -> s32
// ---------------------------------------------------------------------------
__device__ __forceinline__ void mma_s8(int* d, uint32_t a0, uint32_t a1, uint32_t a2, uint32_t a3,
                                       uint32_t b0, uint32_t b1) {
    asm volatile("mma.sync.aligned.m16n8k32.row.col.s32.s8.s8.s32 "
                 "{%0,%1,%2,%3}, {%4,%5,%6,%7}, {%8,%9}, {%0,%1,%2,%3};"
                 : "+r"(d[0]), "+r"(d[1]), "+r"(d[2]), "+r"(d[3])
                 : "r"(a0), "r"(a1), "r"(a2), "r"(a3), "r"(b0), "r"(b1));
}

// ---------------------------------------------------------------------------
// GEMM1: act[dst, i] = silu(g)*u over 32-token tiles. grid (128, E, 2)
// ---------------------------------------------------------------------------
#define G1_SMEM (TT * H_ + 256)
__global__ __launch_bounds__(256) void gemm1_kernel(const float* __restrict__ s13_all) {
    int e = blockIdx.y;
    int cnt = g_cnt[e];
    int base = blockIdx.x * TT;
    if (base >= cnt) return;
    int nt = min(TT, cnt - base);
    int ic = blockIdx.z;   // i-half: tiles [ic*88, ic*88+88)

    extern __shared__ char smem[];
    int8_t* q_tile = (int8_t*)smem;
    float* sin_s = (float*)(smem + TT * H_);
    int* dst_s = (int*)(sin_s + TT);
    int tid = threadIdx.x;
    if (tid < TT) {
        int packed = (tid < nt) ? g_tok[e][base + tid] : g_tok[e][base];
        dst_s[tid] = packed;
        sin_s[tid] = g_sin[packed >> 1];
    }
    __syncthreads();
    // stage q rows swizzled (16B-block XOR by row&7 -> conflict-free frag LDS)
    for (int idx = tid; idx < TT * 128; idx += 256) {
        int tt = idx >> 7, kk = idx & 127;
        int4 v = ((const int4*)(g_qin + (size_t)(dst_s[tt] >> 1) * H_))[kk];
        *(int4*)(q_tile + tt * H_ + ((kk * 16) ^ ((tt & 7) << 4))) = v;
    }
    __syncthreads();

    const int8_t* w13 = g_w13 + (size_t)e * TWOI * H_;
    const float* s13 = s13_all + (size_t)e * TWOI;
    int warp = tid >> 5, lane = tid & 31;
    int mh = warp & 1, ng = warp >> 1;       // 2 m-halves x 4 n-groups
    int arow = mh * 16 + (lane >> 2);
    int sw = (arow & 7) << 4;
    int kc = (lane & 3) * 4;
    const int8_t* ap = q_tile + arow * H_;
    const int8_t* ap8 = q_tile + (arow + 8) * H_;

    for (int chunk = 0; chunk < 3; ++chunk) {
        int nc = (chunk < 2) ? 8 : 6;        // 22 tiles per warp: 8+8+6
        int i8_0 = ic * 88 + ng * 22 + chunk * 8;
        int accg[8][4], accu[8][4];
#pragma unroll
        for (int c = 0; c < 8; ++c)
#pragma unroll
            for (int r = 0; r < 4; ++r) { accg[c][r] = 0; accu[c][r] = 0; }
        const int8_t* gbase = w13 + (size_t)(i8_0 * 8 + (lane >> 2)) * H_ + kc;
        const int8_t* ubase = gbase + (size_t)I_ * H_;
        for (int ks = 0; ks < 64; ++ks) {
            int k = ks * 32;
            uint32_t a0 = *(const uint32_t*)(ap + ((k + kc) ^ sw));
            uint32_t a1 = *(const uint32_t*)(ap8 + ((k + kc) ^ sw));
            uint32_t a2 = *(const uint32_t*)(ap + ((k + kc + 16) ^ sw));
            uint32_t a3 = *(const uint32_t*)(ap8 + ((k + kc + 16) ^ sw));
#pragma unroll
            for (int c = 0; c < 8; ++c) {
                if (c < nc) {
                    uint32_t b0 = *(const uint32_t*)(gbase + (size_t)c * 8 * H_ + k);
                    uint32_t b1 = *(const uint32_t*)(gbase + (size_t)c * 8 * H_ + k + 16);
                    mma_s8(accg[c], a0, a1, a2, a3, b0, b1);
                    uint32_t u0 = *(const uint32_t*)(ubase + (size_t)c * 8 * H_ + k);
                    uint32_t u1 = *(const uint32_t*)(ubase + (size_t)c * 8 * H_ + k + 16);
                    mma_s8(accu[c], a0, a1, a2, a3, u0, u1);
                }
            }
        }
#pragma unroll
        for (int c = 0; c < 8; ++c) {
            if (c < nc) {
                int col0 = (i8_0 + c) * 8 + (lane & 3) * 2;
#pragma unroll
                for (int r = 0; r < 4; ++r) {
                    int rrow = arow + ((r >= 2) ? 8 : 0);
                    int col = col0 + (r & 1);
                    float si = sin_s[rrow];
                    float g = (float)accg[c][r] * si * s13[col];
                    float u = (float)accu[c][r] * si * s13[col + I_];
                    float sig = __fdiv_rn(1.f, 1.f + expf(-g));
                    g_act[(size_t)dst_s[rrow] * I_ + col] = g * sig * u;
                }
            }
        }
    }
}

// ---------------------------------------------------------------------------
// Requant: per-slot absmax -> scale -> int8
// ---------------------------------------------------------------------------
__global__ __launch_bounds__(128) void requant_kernel() {
    int dst = blockIdx.x;
    const float* a = g_act + (size_t)dst * I_;
    int tid = threadIdx.x;
    float m = 0.f;
    for (int i = tid; i < I_; i += 128) m = fmaxf(m, fabsf(a[i]));
    __shared__ float red[4];
#pragma unroll
    for (int off = 16; off; off >>= 1) m = fmaxf(m, __shfl_down_sync(0xffffffffu, m, off));
    if ((tid & 31) == 0) red[tid >> 5] = m;
    __syncthreads();
    float mm = fmaxf(fmaxf(red[0], red[1]), fmaxf(red[2], red[3]));
    float sa = fmaxf(__fdiv_rn(mm, 127.f), 1e-8f);
    if (tid == 0) g_sa[dst] = sa;
    int8_t* q = g_qact + (size_t)dst * I_;
    for (int i = tid; i < I_; i += 128) {
        float v = fminf(fmaxf(rintf(__fdiv_rn(a[i], sa)), -127.f), 127.f);
        q[i] = (int8_t)v;
    }
}

// ---------------------------------------------------------------------------
// GEMM2: partial[dst, h] = gate * (acc * sa * s2w). grid (128, E)
// ---------------------------------------------------------------------------
#define G2_SMEM (TT * I_ + 512)
__global__ __launch_bounds__(256) void gemm2_kernel(const float* __restrict__ s2_all) {
    int e = blockIdx.y;
    int cnt = g_cnt[e];
    int base = blockIdx.x * TT;
    if (base >= cnt) return;
    int nt = min(TT, cnt - base);

    extern __shared__ char smem[];
    int8_t* qa = (int8_t*)smem;
    float* sa_s = (float*)(smem + TT * I_);
    float* gate_s = sa_s + TT;
    int* dst_s = (int*)(gate_s + TT);
    int tid = threadIdx.x;
    if (tid < TT) {
        int packed; float gv;
        if (tid < nt) { packed = g_tok[e][base + tid]; gv = g_gate_arr[e][base + tid]; }
        else          { packed = g_tok[e][base];       gv = 0.f; }
        dst_s[tid] = packed;
        gate_s[tid] = gv;
        sa_s[tid] = g_sa[packed];
    }
    __syncthreads();
    for (int idx = tid; idx < TT * 88; idx += 256) {
        int tt = idx / 88, kk = idx - tt * 88;
        int4 v = ((const int4*)(g_qact + (size_t)dst_s[tt] * I_))[kk];
        *(int4*)(qa + tt * I_ + ((kk * 16) ^ ((tt & 7) << 4))) = v;
    }
    __syncthreads();

    const int8_t* w2 = g_w2 + (size_t)e * H_ * I_;
    const float* s2w = s2_all + (size_t)e * H_;
    int warp = tid >> 5, lane = tid & 31;
    int mh = warp & 1, ng = warp >> 1;
    int arow = mh * 16 + (lane >> 2);
    int sw = (arow & 7) << 4;
    int kc = (lane & 3) * 4;
    const int8_t* ap = qa + arow * I_;
    const int8_t* ap8 = qa + (arow + 8) * I_;

    for (int chunk = 0; chunk < 8; ++chunk) {
        int h8_0 = ng * 64 + chunk * 8;     // 256 n-tiles over 4 groups
        int acc[8][4];
#pragma unroll
        for (int c = 0; c < 8; ++c)
#pragma unroll
            for (int r = 0; r < 4; ++r) acc[c][r] = 0;
        const int8_t* bbase = w2 + (size_t)(h8_0 * 8 + (lane >> 2)) * I_ + kc;
        for (int ks = 0; ks < 44; ++ks) {
            int k = ks * 32;
            uint32_t a0 = *(const uint32_t*)(ap + ((k + kc) ^ sw));
            uint32_t a1 = *(const uint32_t*)(ap8 + ((k + kc) ^ sw));
            uint32_t a2 = *(const uint32_t*)(ap + ((k + kc + 16) ^ sw));
            uint32_t a3 = *(const uint32_t*)(ap8 + ((k + kc + 16) ^ sw));
#pragma unroll
            for (int c = 0; c < 8; ++c) {
                uint32_t b0 = *(const uint32_t*)(bbase + (size_t)c * 8 * I_ + k);
                uint32_t b1 = *(const uint32_t*)(bbase + (size_t)c * 8 * I_ + k + 16);
                mma_s8(acc[c], a0, a1, a2, a3, b0, b1);
            }
        }
#pragma unroll
        for (int c = 0; c < 8; ++c) {
            int col0 = (h8_0 + c) * 8 + (lane & 3) * 2;
#pragma unroll
            for (int r = 0; r < 4; ++r) {
                int rrow = arow + ((r >= 2) ? 8 : 0);
                if (rrow < nt) {
                    int h = col0 + (r & 1);
                    float h2 = (float)acc[c][r] * sa_s[rrow] * s2w[h];
                    g_partial[(size_t)dst_s[rrow] * H_ + h] = gate_s[rrow] * h2;
                }
            }
        }
    }
}

// ---------------------------------------------------------------------------
__global__ __launch_bounds__(256) void finalize_kernel(float* __restrict__ out) {
    size_t idx = (size_t)blockIdx.x * 256 + threadIdx.x;
    size_t t = idx >> 11;
    size_t h = idx & 2047;
    out[idx] = g_partial[(t * 2) * H_ + h] + g_partial[(t * 2 + 1) * H_ + h];
}

extern "C" void kernel_launch(void* const* d_in, const int* in_sizes, int n_in,
                              void* d_out, int out_size) {
    const float* hid = nullptr;
    const float* gw = nullptr;
    const void* w13raw = nullptr;
    const float* s13 = nullptr;
    const void* w2raw = nullptr;
    const float* s2 = nullptr;
    for (int i = 0; i < n_in; ++i) {
        long long s = in_sizes[i];
        if (s == 8388608LL || s == 33554432LL) hid = (const float*)d_in[i];
        else if (s == 46137344LL || s == 184549376LL) w13raw = d_in[i];
        else if (s == 22528LL || s == 90112LL) s13 = (const float*)d_in[i];
        else if (s == 23068672LL || s == 92274688LL) w2raw = d_in[i];
        else if (s == 16384LL || s == 65536LL) {
            if (!gw) gw = (const float*)d_in[i];
            else s2 = (const float*)d_in[i];
        }
    }
    if (n_in >= 6) {
        if (!hid)    hid = (const float*)d_in[0];
        if (!gw)     gw = (const float*)d_in[1];
        if (!w13raw) w13raw = d_in[2];
        if (!s13)    s13 = (const float*)d_in[3];
        if (!w2raw)  w2raw = d_in[4];
        if (!s2)     s2 = (const float*)d_in[5];
    }
    float* out = (float*)d_out;

    cudaFuncSetAttribute(gemm1_kernel, cudaFuncAttributeMaxDynamicSharedMemorySize, G1_SMEM);
    cudaFuncSetAttribute(gemm2_kernel, cudaFuncAttributeMaxDynamicSharedMemorySize, G2_SMEM);

    init_kernel<<<1, 32>>>(w13raw);                       // 1
    convert_w13_kernel<<<8192, 256>>>(w13raw);            // 2
    convert_w2_kernel<<<8192, 256>>>(w2raw);              // 3
    gate_kernel<<<T_, 256>>>(hid, gw);                    // 4
    quant_kernel<<<T_, 256>>>(hid);                       // 5
    dim3 g1(T_ / TT, E_, 2);
    gemm1_kernel<<<g1, 256, G1_SMEM>>>(s13);              // 6 (ncu -s 5)
    requant_kernel<<<T_ * 2, 128>>>();                    // 7
    dim3 g2(T_ / TT, E_);
    gemm2_kernel<<<g2, 256, G2_SMEM>>>(s2);               // 8
    finalize_kernel<<<(T_ * H_) / 256, 256>>>(out);       // 9
}

// round 8
// speedup vs baseline: 3.0571x; 1.4029x over previous
#include <cuda_runtime.h>
#include <cstdint>
#include <math.h>

#define T_    4096
#define H_    2048
#define I_    1408
#define E_    8
#define TWOI  2816

// ---------------- scratch ----------------
__device__ int8_t g_qin[(size_t)T_ * H_];
__device__ float  g_sin[T_];
__device__ int    g_cnt[E_];
__device__ int    g_tok[E_][T_];
__device__ float  g_gate_arr[E_][T_];
__device__ float  g_partial[(size_t)T_ * 2 * H_];
__device__ int8_t g_w13[(size_t)E_ * TWOI * H_];
__device__ int8_t g_w2[(size_t)E_ * H_ * I_];
__device__ float  g_act[(size_t)T_ * 2 * I_];
__device__ int8_t g_qact[(size_t)T_ * 2 * I_];
__device__ float  g_sa[T_ * 2];

// ---------------- helpers ----------------
__device__ __forceinline__ uint32_t smem_u32(const void* p) {
    uint32_t a;
    asm("{ .reg .u64 t; cvta.to.shared.u64 t, %1; cvt.u32.u64 %0, t; }" : "=r"(a) : "l"(p));
    return a;
}
#define CP16(dst, src) asm volatile("cp.async.cg.shared.global [%0], [%1], 16;" :: "r"(dst), "l"(src))
#define CP_COMMIT()    asm volatile("cp.async.commit_group;" ::: "memory")
#define CP_WAIT1()     asm volatile("cp.async.wait_group 1;" ::: "memory")

__device__ __forceinline__ void mma_s8(int* d, uint32_t a0, uint32_t a1, uint32_t a2, uint32_t a3,
                                       uint32_t b0, uint32_t b1) {
    asm volatile("mma.sync.aligned.m16n8k32.row.col.s32.s8.s8.s32 "
                 "{%0,%1,%2,%3}, {%4,%5,%6,%7}, {%8,%9}, {%0,%1,%2,%3};"
                 : "+r"(d[0]), "+r"(d[1]), "+r"(d[2]), "+r"(d[3])
                 : "r"(a0), "r"(a1), "r"(a2), "r"(a3), "r"(b0), "r"(b1));
}

// ---------------- weight conversion ----------------
__device__ __forceinline__ char4 conv_elem(const void* __restrict__ src, int idx, int mode) {
    if (mode == 1) {
        int4 v = ((const int4*)src)[idx];
        return make_char4((signed char)v.x, (signed char)v.y, (signed char)v.z, (signed char)v.w);
    } else if (mode == 2) {
        float4 v = ((const float4*)src)[idx];
        return make_char4((signed char)(int)v.x, (signed char)(int)v.y,
                          (signed char)(int)v.z, (signed char)(int)v.w);
    }
    return ((const char4*)src)[idx];
}
__device__ __forceinline__ int block_detect_mode(const void* src) {
    int tid = threadIdx.x;
    int v = ((const int*)src)[tid];
    float f = ((const float*)src)[tid];
    int n32 = __syncthreads_count(v >= -127 && v <= 127);
    int nf = __syncthreads_count(fabsf(f) <= 127.f && rintf(f) == f);
    return (n32 >= 250) ? 1 : ((nf >= 250) ? 2 : 0);
}
#define N4_W13 ((E_ * TWOI * H_) / 4)
#define N4_W2  ((E_ * H_ * I_) / 4)

__global__ __launch_bounds__(256) void convert_w13_kernel(const void* __restrict__ src) {
    int mode = block_detect_mode(src);
    for (int idx = blockIdx.x * 256 + threadIdx.x; idx < N4_W13; idx += gridDim.x * 256)
        ((char4*)g_w13)[idx] = conv_elem(src, idx, mode);
    if (blockIdx.x == 0 && threadIdx.x < E_) g_cnt[threadIdx.x] = 0;
}
__global__ __launch_bounds__(256) void convert_w2_kernel(const void* __restrict__ src) {
    int mode = block_detect_mode(src);
    for (int idx = blockIdx.x * 256 + threadIdx.x; idx < N4_W2; idx += gridDim.x * 256)
        ((char4*)g_w2)[idx] = conv_elem(src, idx, mode);
}

// ---------------- gate + quantize ----------------
__global__ __launch_bounds__(256) void gatequant_kernel(const float* __restrict__ hid,
                                                        const float* __restrict__ gw) {
    int t = blockIdx.x;
    const float* x = hid + (size_t)t * H_;
    float part[E_];
#pragma unroll
    for (int e = 0; e < E_; ++e) part[e] = 0.f;
    float amax = 0.f;
    for (int j = threadIdx.x; j < H_; j += 256) {
        float v = x[j];
        amax = fmaxf(amax, fabsf(v));
#pragma unroll
        for (int e = 0; e < E_; ++e) part[e] = fmaf(v, gw[e * H_ + j], part[e]);
    }
#pragma unroll
    for (int off = 16; off; off >>= 1) {
        amax = fmaxf(amax, __shfl_down_sync(0xffffffffu, amax, off));
#pragma unroll
        for (int e = 0; e < E_; ++e) part[e] += __shfl_down_sync(0xffffffffu, part[e], off);
    }
    __shared__ float red[8][E_ + 1];
    __shared__ float s_sh;
    int warp = threadIdx.x >> 5, lane = threadIdx.x & 31;
    if (lane == 0) {
#pragma unroll
        for (int e = 0; e < E_; ++e) red[warp][e] = part[e];
        red[warp][E_] = amax;
    }
    __syncthreads();
    if (threadIdx.x == 0) {
        float l[E_]; float am = 0.f;
#pragma unroll
        for (int e = 0; e < E_; ++e) l[e] = 0.f;
        for (int w = 0; w < 8; ++w) {
#pragma unroll
            for (int e = 0; e < E_; ++e) l[e] += red[w][e];
            am = fmaxf(am, red[w][E_]);
        }
        float b1 = -1e30f, b2 = -1e30f; int i1 = 0, i2 = 0;
#pragma unroll
        for (int e = 0; e < E_; ++e) {
            float v = l[e];
            if (v > b1) { b2 = b1; i2 = i1; b1 = v; i1 = e; }
            else if (v > b2) { b2 = v; i2 = e; }
        }
        float e2v = expf(b2 - b1);
        float inv = __fdiv_rn(1.f, 1.f + e2v);
        float s = fmaxf(__fdiv_rn(am, 127.f), 1e-8f);
        g_sin[t] = s; s_sh = s;
        int p0 = atomicAdd(&g_cnt[i1], 1);
        g_tok[i1][p0] = t * 2 + 0; g_gate_arr[i1][p0] = inv;
        int p1 = atomicAdd(&g_cnt[i2], 1);
        g_tok[i2][p1] = t * 2 + 1; g_gate_arr[i2][p1] = e2v * inv;
    }
    __syncthreads();
    float s = s_sh;
    const float4* xv = (const float4*)x;
    char4* q = (char4*)(g_qin + (size_t)t * H_);
    for (int j = threadIdx.x; j < H_ / 4; j += 256) {
        float4 v = xv[j];
        float a = fminf(fmaxf(rintf(__fdiv_rn(v.x, s)), -127.f), 127.f);
        float b = fminf(fmaxf(rintf(__fdiv_rn(v.y, s)), -127.f), 127.f);
        float c = fminf(fmaxf(rintf(__fdiv_rn(v.z, s)), -127.f), 127.f);
        float d = fminf(fmaxf(rintf(__fdiv_rn(v.w, s)), -127.f), 127.f);
        q[j] = make_char4((signed char)a, (signed char)b, (signed char)c, (signed char)d);
    }
}

// ===========================================================================
// GEMM1: M=128 tokens x 64 i-cols (g and u), K=2048. cp.async 3-stage pipe.
// smem stage: A 128x80 (10240) + B 128x80 (10240, rows 0-63=g, 64-127=u)
// grid (32, E, 22), 256 threads.
// ===========================================================================
#define PAD    80
#define STAGE1 20480
#define G1_META (3 * STAGE1)
#define G1_SMEM (G1_META + 1024)
#define NS1    32

__global__ __launch_bounds__(256) void gemm1_mma(const float* __restrict__ s13_all) {
    int e = blockIdx.y;
    int cnt = g_cnt[e];
    int m0 = blockIdx.x * 128;
    if (m0 >= cnt) return;
    int nt = min(128, cnt - m0);
    int z = blockIdx.z;           // 64 i-cols: [z*64, z*64+64)

    extern __shared__ char smem[];
    uint32_t sb = smem_u32(smem);
    int* dst_s = (int*)(smem + G1_META);
    float* sin_s = (float*)(smem + G1_META + 512);
    int tid = threadIdx.x;

    if (tid < 128) {
        int packed = (tid < nt) ? g_tok[e][m0 + tid] : g_tok[e][m0];
        dst_s[tid] = packed;
        sin_s[tid] = g_sin[packed >> 1];
    }
    __syncthreads();

    const int8_t* w13 = g_w13 + (size_t)e * TWOI * H_;
    // per-thread cp.async assignment: row tid>>1, bytes (tid&1)*32 .. +31
    int rA = tid >> 1, cA = (tid & 1) * 32;
    const int8_t* srcA = g_qin + (size_t)(dst_s[rA] >> 1) * H_ + cA;
    const int8_t* srcB = (rA < 64)
        ? w13 + (size_t)(z * 64 + rA) * H_ + cA
        : w13 + (size_t)(I_ + z * 64 + (rA - 64)) * H_ + cA;
    uint32_t dA = sb + rA * PAD + cA;
    uint32_t dB = sb + 10240 + rA * PAD + cA;

#pragma unroll
    for (int s = 0; s < 2; ++s) {
        CP16(dA + s * STAGE1, srcA + s * 64);
        CP16(dA + s * STAGE1 + 16, srcA + s * 64 + 16);
        CP16(dB + s * STAGE1, srcB + s * 64);
        CP16(dB + s * STAGE1 + 16, srcB + s * 64 + 16);
        CP_COMMIT();
    }

    int warp = tid >> 5, lane = tid & 31;
    int wm = warp & 3, wn = warp >> 2;
    int sub = lane >> 2, q4 = (lane & 3) * 4;
    int accg[2][4][4], accu[2][4][4];
#pragma unroll
    for (int mt = 0; mt < 2; ++mt)
#pragma unroll
        for (int n8 = 0; n8 < 4; ++n8)
#pragma unroll
            for (int r = 0; r < 4; ++r) { accg[mt][n8][r] = 0; accu[mt][n8][r] = 0; }

    for (int ks = 0; ks < NS1; ++ks) {
        CP_WAIT1();
        __syncthreads();
        const char* As = smem + (ks % 3) * STAGE1;
        const char* Bs = As + 10240;
#pragma unroll
        for (int kk = 0; kk < 64; kk += 32) {
            uint32_t a[2][4];
#pragma unroll
            for (int mt = 0; mt < 2; ++mt) {
                const char* ar = As + (wm * 32 + mt * 16 + sub) * PAD + kk + q4;
                a[mt][0] = *(const uint32_t*)(ar);
                a[mt][1] = *(const uint32_t*)(ar + 8 * PAD);
                a[mt][2] = *(const uint32_t*)(ar + 16);
                a[mt][3] = *(const uint32_t*)(ar + 8 * PAD + 16);
            }
#pragma unroll
            for (int n8 = 0; n8 < 4; ++n8) {
                const char* bg = Bs + (wn * 32 + n8 * 8 + sub) * PAD + kk + q4;
                uint32_t g0 = *(const uint32_t*)(bg);
                uint32_t g1 = *(const uint32_t*)(bg + 16);
                uint32_t u0 = *(const uint32_t*)(bg + 64 * PAD);
                uint32_t u1 = *(const uint32_t*)(bg + 64 * PAD + 16);
#pragma unroll
                for (int mt = 0; mt < 2; ++mt) {
                    mma_s8(accg[mt][n8], a[mt][0], a[mt][1], a[mt][2], a[mt][3], g0, g1);
                    mma_s8(accu[mt][n8], a[mt][0], a[mt][1], a[mt][2], a[mt][3], u0, u1);
                }
            }
        }
        if (ks + 2 < NS1) {
            int s = (ks + 2) % 3;
            int kb = (ks + 2) * 64;
            CP16(dA + s * STAGE1, srcA + kb);
            CP16(dA + s * STAGE1 + 16, srcA + kb + 16);
            CP16(dB + s * STAGE1, srcB + kb);
            CP16(dB + s * STAGE1 + 16, srcB + kb + 16);
        }
        CP_COMMIT();
    }

    // epilogue: silu(g)*u -> g_act
    const float* s13 = s13_all + (size_t)e * TWOI + z * 64;
#pragma unroll
    for (int mt = 0; mt < 2; ++mt) {
#pragma unroll
        for (int n8 = 0; n8 < 4; ++n8) {
            int col = wn * 32 + n8 * 8 + (lane & 3) * 2;
            float sg0 = s13[col], sg1 = s13[col + 1];
            float su0 = s13[col + I_], su1 = s13[col + I_ + 1];
#pragma unroll
            for (int h2 = 0; h2 < 2; ++h2) {
                int row = wm * 32 + mt * 16 + sub + h2 * 8;
                if (row < nt) {
                    float si = sin_s[row];
                    float g0 = (float)accg[mt][n8][h2 * 2 + 0] * si * sg0;
                    float g1 = (float)accg[mt][n8][h2 * 2 + 1] * si * sg1;
                    float u0 = (float)accu[mt][n8][h2 * 2 + 0] * si * su0;
                    float u1 = (float)accu[mt][n8][h2 * 2 + 1] * si * su1;
                    float a0 = g0 * __fdiv_rn(1.f, 1.f + expf(-g0)) * u0;
                    float a1 = g1 * __fdiv_rn(1.f, 1.f + expf(-g1)) * u1;
                    *(float2*)(g_act + (size_t)dst_s[row] * I_ + z * 64 + col) =
                        make_float2(a0, a1);
                }
            }
        }
    }
}

// ---------------- requant ----------------
__global__ __launch_bounds__(128) void requant_kernel() {
    int dst = blockIdx.x;
    const float* a = g_act + (size_t)dst * I_;
    int tid = threadIdx.x;
    float m = 0.f;
    for (int i = tid; i < I_; i += 128) m = fmaxf(m, fabsf(a[i]));
    __shared__ float red[4];
#pragma unroll
    for (int off = 16; off; off >>= 1) m = fmaxf(m, __shfl_down_sync(0xffffffffu, m, off));
    if ((tid & 31) == 0) red[tid >> 5] = m;
    __syncthreads();
    float mm = fmaxf(fmaxf(red[0], red[1]), fmaxf(red[2], red[3]));
    float sa = fmaxf(__fdiv_rn(mm, 127.f), 1e-8f);
    if (tid == 0) g_sa[dst] = sa;
    int8_t* q = g_qact + (size_t)dst * I_;
    for (int i = tid; i < I_; i += 128) {
        float v = fminf(fmaxf(rintf(__fdiv_rn(a[i], sa)), -127.f), 127.f);
        q[i] = (int8_t)v;
    }
}

// ===========================================================================
// GEMM2: M=128 tokens x 128 h-cols, K=1408. grid (32, E, 16), 256 threads.
// ===========================================================================
#define STAGE2 20480
#define G2_META (3 * STAGE2)
#define G2_SMEM (G2_META + 2048)
#define NS2    22

__global__ __launch_bounds__(256) void gemm2_mma(const float* __restrict__ s2_all) {
    int e = blockIdx.y;
    int cnt = g_cnt[e];
    int m0 = blockIdx.x * 128;
    if (m0 >= cnt) return;
    int nt = min(128, cnt - m0);
    int z = blockIdx.z;           // 128 h-cols: [z*128, ...)

    extern __shared__ char smem[];
    uint32_t sb = smem_u32(smem);
    int* dst_s = (int*)(smem + G2_META);
    float* sa_s = (float*)(smem + G2_META + 512);
    float* gate_s = (float*)(smem + G2_META + 1024);
    int tid = threadIdx.x;

    if (tid < 128) {
        int packed; float gv;
        if (tid < nt) { packed = g_tok[e][m0 + tid]; gv = g_gate_arr[e][m0 + tid]; }
        else          { packed = g_tok[e][m0];       gv = 0.f; }
        dst_s[tid] = packed;
        gate_s[tid] = gv;
        sa_s[tid] = g_sa[packed];
    }
    __syncthreads();

    const int8_t* w2 = g_w2 + (size_t)e * H_ * I_;
    int rA = tid >> 1, cA = (tid & 1) * 32;
    const int8_t* srcA = g_qact + (size_t)dst_s[rA] * I_ + cA;
    const int8_t* srcB = w2 + (size_t)(z * 128 + rA) * I_ + cA;
    uint32_t dA = sb + rA * PAD + cA;
    uint32_t dB = sb + 10240 + rA * PAD + cA;

#pragma unroll
    for (int s = 0; s < 2; ++s) {
        CP16(dA + s * STAGE2, srcA + s * 64);
        CP16(dA + s * STAGE2 + 16, srcA + s * 64 + 16);
        CP16(dB + s * STAGE2, srcB + s * 64);
        CP16(dB + s * STAGE2 + 16, srcB + s * 64 + 16);
        CP_COMMIT();
    }

    int warp = tid >> 5, lane = tid & 31;
    int wm = warp & 3, wn = warp >> 2;
    int sub = lane >> 2, q4 = (lane & 3) * 4;
    int acc[2][8][4];
#pragma unroll
    for (int mt = 0; mt < 2; ++mt)
#pragma unroll
        for (int n8 = 0; n8 < 8; ++n8)
#pragma unroll
            for (int r = 0; r < 4; ++r) acc[mt][n8][r] = 0;

    for (int ks = 0; ks < NS2; ++ks) {
        CP_WAIT1();
        __syncthreads();
        const char* As = smem + (ks % 3) * STAGE2;
        const char* Bs = As + 10240;
#pragma unroll
        for (int kk = 0; kk < 64; kk += 32) {
            uint32_t a[2][4];
#pragma unroll
            for (int mt = 0; mt < 2; ++mt) {
                const char* ar = As + (wm * 32 + mt * 16 + sub) * PAD + kk + q4;
                a[mt][0] = *(const uint32_t*)(ar);
                a[mt][1] = *(const uint32_t*)(ar + 8 * PAD);
                a[mt][2] = *(const uint32_t*)(ar + 16);
                a[mt][3] = *(const uint32_t*)(ar + 8 * PAD + 16);
            }
#pragma unroll
            for (int n8 = 0; n8 < 8; ++n8) {
                const char* br = Bs + (wn * 64 + n8 * 8 + sub) * PAD + kk + q4;
                uint32_t b0 = *(const uint32_t*)(br);
                uint32_t b1 = *(const uint32_t*)(br + 16);
#pragma unroll
                for (int mt = 0; mt < 2; ++mt)
                    mma_s8(acc[mt][n8], a[mt][0], a[mt][1], a[mt][2], a[mt][3], b0, b1);
            }
        }
        if (ks + 2 < NS2) {
            int s = (ks + 2) % 3;
            int kb = (ks + 2) * 64;
            CP16(dA + s * STAGE2, srcA + kb);
            CP16(dA + s * STAGE2 + 16, srcA + kb + 16);
            CP16(dB + s * STAGE2, srcB + kb);
            CP16(dB + s * STAGE2 + 16, srcB + kb + 16);
        }
        CP_COMMIT();
    }

    const float* s2w = s2_all + (size_t)e * H_ + z * 128;
#pragma unroll
    for (int mt = 0; mt < 2; ++mt) {
#pragma unroll
        for (int n8 = 0; n8 < 8; ++n8) {
            int col = wn * 64 + n8 * 8 + (lane & 3) * 2;
            float w0 = s2w[col], w1 = s2w[col + 1];
#pragma unroll
            for (int h2 = 0; h2 < 2; ++h2) {
                int row = wm * 32 + mt * 16 + sub + h2 * 8;
                if (row < nt) {
                    float sc = sa_s[row] * gate_s[row];
                    float v0 = (float)acc[mt][n8][h2 * 2 + 0] * sc * w0;
                    float v1 = (float)acc[mt][n8][h2 * 2 + 1] * sc * w1;
                    *(float2*)(g_partial + (size_t)dst_s[row] * H_ + z * 128 + col) =
                        make_float2(v0, v1);
                }
            }
        }
    }
}

// ---------------- finalize ----------------
__global__ __launch_bounds__(256) void finalize_kernel(float* __restrict__ out) {
    size_t idx = (size_t)blockIdx.x * 256 + threadIdx.x;
    size_t t = idx >> 11;
    size_t h = idx & 2047;
    out[idx] = g_partial[(t * 2) * H_ + h] + g_partial[(t * 2 + 1) * H_ + h];
}

// ---------------------------------------------------------------------------
extern "C" void kernel_launch(void* const* d_in, const int* in_sizes, int n_in,
                              void* d_out, int out_size) {
    const float* hid = nullptr;
    const float* gw = nullptr;
    const void* w13raw = nullptr;
    const float* s13 = nullptr;
    const void* w2raw = nullptr;
    const float* s2 = nullptr;
    for (int i = 0; i < n_in; ++i) {
        long long s = in_sizes[i];
        if (s == 8388608LL || s == 33554432LL) hid = (const float*)d_in[i];
        else if (s == 46137344LL || s == 184549376LL) w13raw = d_in[i];
        else if (s == 22528LL || s == 90112LL) s13 = (const float*)d_in[i];
        else if (s == 23068672LL || s == 92274688LL) w2raw = d_in[i];
        else if (s == 16384LL || s == 65536LL) {
            if (!gw) gw = (const float*)d_in[i];
            else s2 = (const float*)d_in[i];
        }
    }
    if (n_in >= 6) {
        if (!hid)    hid = (const float*)d_in[0];
        if (!gw)     gw = (const float*)d_in[1];
        if (!w13raw) w13raw = d_in[2];
        if (!s13)    s13 = (const float*)d_in[3];
        if (!w2raw)  w2raw = d_in[4];
        if (!s2)     s2 = (const float*)d_in[5];
    }
    float* out = (float*)d_out;

    cudaFuncSetAttribute(gemm1_mma, cudaFuncAttributeMaxDynamicSharedMemorySize, G1_SMEM);
    cudaFuncSetAttribute(gemm2_mma, cudaFuncAttributeMaxDynamicSharedMemorySize, G2_SMEM);

    convert_w13_kernel<<<8192, 256>>>(w13raw);            // 1
    convert_w2_kernel<<<8192, 256>>>(w2raw);              // 2
    gatequant_kernel<<<T_, 256>>>(hid, gw);               // 3
    dim3 g1(32, E_, 22);
    gemm1_mma<<<g1, 256, G1_SMEM>>>(s13);                 // 4
    requant_kernel<<<T_ * 2, 128>>>();                    // 5
    dim3 g2(32, E_, 16);
    gemm2_mma<<<g2, 256, G2_SMEM>>>(s2);                  // 6
    finalize_kernel<<<(T_ * H_) / 256, 256>>>(out);       // 7
}

// round 9
// speedup vs baseline: 3.5987x; 1.1772x over previous
#include <cuda_runtime.h>
#include <cstdint>
#include <math.h>

#define T_    4096
#define H_    2048
#define I_    1408
#define E_    8
#define TWOI  2816

// ---------------- scratch ----------------
__device__ int8_t g_qin[(size_t)T_ * H_];
__device__ float  g_sin[T_];
__device__ int    g_cnt[E_];
__device__ int    g_tok[E_][T_];
__device__ float  g_gate_arr[E_][T_];
__device__ int8_t g_w13[(size_t)E_ * TWOI * H_];
__device__ int8_t g_w2[(size_t)E_ * H_ * I_];
__device__ float  g_act[(size_t)T_ * 2 * I_];
__device__ int8_t g_qact[(size_t)T_ * 2 * I_];
__device__ float  g_sa[T_ * 2];

// ---------------- helpers ----------------
__device__ __forceinline__ uint32_t smem_u32(const void* p) {
    uint32_t a;
    asm("{ .reg .u64 t; cvta.to.shared.u64 t, %1; cvt.u32.u64 %0, t; }" : "=r"(a) : "l"(p));
    return a;
}
#define CP16(dst, src) asm volatile("cp.async.cg.shared.global [%0], [%1], 16;" :: "r"(dst), "l"(src))
#define CP_COMMIT()    asm volatile("cp.async.commit_group;" ::: "memory")
#define CP_WAIT1()     asm volatile("cp.async.wait_group 1;" ::: "memory")

__device__ __forceinline__ void mma_s8(int* d, uint32_t a0, uint32_t a1, uint32_t a2, uint32_t a3,
                                       uint32_t b0, uint32_t b1) {
    asm volatile("mma.sync.aligned.m16n8k32.row.col.s32.s8.s8.s32 "
                 "{%0,%1,%2,%3}, {%4,%5,%6,%7}, {%8,%9}, {%0,%1,%2,%3};"
                 : "+r"(d[0]), "+r"(d[1]), "+r"(d[2]), "+r"(d[3])
                 : "r"(a0), "r"(a1), "r"(a2), "r"(a3), "r"(b0), "r"(b1));
}

// ---------------- weight conversion ----------------
__device__ __forceinline__ char4 conv_elem(const void* __restrict__ src, int idx, int mode) {
    if (mode == 1) {
        int4 v = ((const int4*)src)[idx];
        return make_char4((signed char)v.x, (signed char)v.y, (signed char)v.z, (signed char)v.w);
    } else if (mode == 2) {
        float4 v = ((const float4*)src)[idx];
        return make_char4((signed char)(int)v.x, (signed char)(int)v.y,
                          (signed char)(int)v.z, (signed char)(int)v.w);
    }
    return ((const char4*)src)[idx];
}
__device__ __forceinline__ int block_detect_mode(const void* src) {
    int tid = threadIdx.x;
    int v = ((const int*)src)[tid];
    float f = ((const float*)src)[tid];
    int n32 = __syncthreads_count(v >= -127 && v <= 127);
    int nf = __syncthreads_count(fabsf(f) <= 127.f && rintf(f) == f);
    return (n32 >= 250) ? 1 : ((nf >= 250) ? 2 : 0);
}
#define N4_W13 ((E_ * TWOI * H_) / 4)
#define N4_W2  ((E_ * H_ * I_) / 4)

__global__ __launch_bounds__(256) void convert_w13_kernel(const void* __restrict__ src) {
    int mode = block_detect_mode(src);
    for (int idx = blockIdx.x * 256 + threadIdx.x; idx < N4_W13; idx += gridDim.x * 256)
        ((char4*)g_w13)[idx] = conv_elem(src, idx, mode);
    if (blockIdx.x == 0 && threadIdx.x < E_) g_cnt[threadIdx.x] = 0;
}
__global__ __launch_bounds__(256) void convert_w2_kernel(const void* __restrict__ src) {
    int mode = block_detect_mode(src);
    for (int idx = blockIdx.x * 256 + threadIdx.x; idx < N4_W2; idx += gridDim.x * 256)
        ((char4*)g_w2)[idx] = conv_elem(src, idx, mode);
}

// ---------------- gate + quantize ----------------
__global__ __launch_bounds__(256) void gatequant_kernel(const float* __restrict__ hid,
                                                        const float* __restrict__ gw) {
    int t = blockIdx.x;
    const float* x = hid + (size_t)t * H_;
    float part[E_];
#pragma unroll
    for (int e = 0; e < E_; ++e) part[e] = 0.f;
    float amax = 0.f;
    for (int j = threadIdx.x; j < H_; j += 256) {
        float v = x[j];
        amax = fmaxf(amax, fabsf(v));
#pragma unroll
        for (int e = 0; e < E_; ++e) part[e] = fmaf(v, gw[e * H_ + j], part[e]);
    }
#pragma unroll
    for (int off = 16; off; off >>= 1) {
        amax = fmaxf(amax, __shfl_down_sync(0xffffffffu, amax, off));
#pragma unroll
        for (int e = 0; e < E_; ++e) part[e] += __shfl_down_sync(0xffffffffu, part[e], off);
    }
    __shared__ float red[8][E_ + 1];
    __shared__ float s_sh;
    int warp = threadIdx.x >> 5, lane = threadIdx.x & 31;
    if (lane == 0) {
#pragma unroll
        for (int e = 0; e < E_; ++e) red[warp][e] = part[e];
        red[warp][E_] = amax;
    }
    __syncthreads();
    if (threadIdx.x == 0) {
        float l[E_]; float am = 0.f;
#pragma unroll
        for (int e = 0; e < E_; ++e) l[e] = 0.f;
        for (int w = 0; w < 8; ++w) {
#pragma unroll
            for (int e = 0; e < E_; ++e) l[e] += red[w][e];
            am = fmaxf(am, red[w][E_]);
        }
        float b1 = -1e30f, b2 = -1e30f; int i1 = 0, i2 = 0;
#pragma unroll
        for (int e = 0; e < E_; ++e) {
            float v = l[e];
            if (v > b1) { b2 = b1; i2 = i1; b1 = v; i1 = e; }
            else if (v > b2) { b2 = v; i2 = e; }
        }
        float e2v = expf(b2 - b1);
        float inv = __fdiv_rn(1.f, 1.f + e2v);
        float s = fmaxf(__fdiv_rn(am, 127.f), 1e-8f);
        g_sin[t] = s; s_sh = s;
        int p0 = atomicAdd(&g_cnt[i1], 1);
        g_tok[i1][p0] = t * 2 + 0; g_gate_arr[i1][p0] = inv;
        int p1 = atomicAdd(&g_cnt[i2], 1);
        g_tok[i2][p1] = t * 2 + 1; g_gate_arr[i2][p1] = e2v * inv;
    }
    __syncthreads();
    float s = s_sh;
    const float4* xv = (const float4*)x;
    char4* q = (char4*)(g_qin + (size_t)t * H_);
    for (int j = threadIdx.x; j < H_ / 4; j += 256) {
        float4 v = xv[j];
        float a = fminf(fmaxf(rintf(__fdiv_rn(v.x, s)), -127.f), 127.f);
        float b = fminf(fmaxf(rintf(__fdiv_rn(v.y, s)), -127.f), 127.f);
        float c = fminf(fmaxf(rintf(__fdiv_rn(v.z, s)), -127.f), 127.f);
        float d = fminf(fmaxf(rintf(__fdiv_rn(v.w, s)), -127.f), 127.f);
        q[j] = make_char4((signed char)a, (signed char)b, (signed char)c, (signed char)d);
    }
}

// ===========================================================================
// GEMM1: M=64 tokens x (64 g + 64 u cols), K=2048. cp.async 3-stage pipe.
// stage: A 64x80 (5120) + B 128x80 (10240). grid (64, E, 22), 256 threads.
// ===========================================================================
#define PAD    80
#define ST1    15360
#define G1_META (3 * ST1)
#define G1_SMEM (G1_META + 768)
#define NS1    32

__global__ __launch_bounds__(256, 3) void gemm1_mma(const float* __restrict__ s13_all) {
    int e = blockIdx.y;
    int cnt = g_cnt[e];
    int m0 = blockIdx.x * 64;
    if (m0 >= cnt) return;
    int nt = min(64, cnt - m0);
    int z = blockIdx.z;           // 64 i-cols: [z*64, z*64+64)

    extern __shared__ char smem[];
    uint32_t sb = smem_u32(smem);
    int* dst_s = (int*)(smem + G1_META);
    float* sin_s = (float*)(smem + G1_META + 256);
    int tid = threadIdx.x;

    if (tid < 64) {
        int packed = (tid < nt) ? g_tok[e][m0 + tid] : g_tok[e][m0];
        dst_s[tid] = packed;
        sin_s[tid] = g_sin[packed >> 1];
    }
    __syncthreads();

    const int8_t* w13 = g_w13 + (size_t)e * TWOI * H_;
    // A staging: row tid>>2 (0..63), 16B chunk (tid&3)
    int rA = tid >> 2, cA = (tid & 3) * 16;
    const int8_t* srcA = g_qin + (size_t)(dst_s[rA] >> 1) * H_ + cA;
    // B staging: row tid>>1 (0..127: 0-63=g, 64-127=u), 32B half (tid&1)
    int rB = tid >> 1, cB = (tid & 1) * 32;
    const int8_t* srcB = (rB < 64)
        ? w13 + (size_t)(z * 64 + rB) * H_ + cB
        : w13 + (size_t)(I_ + z * 64 + (rB - 64)) * H_ + cB;
    uint32_t dA = sb + rA * PAD + cA;
    uint32_t dB = sb + 5120 + rB * PAD + cB;

#pragma unroll
    for (int s = 0; s < 2; ++s) {
        CP16(dA + s * ST1, srcA + s * 64);
        CP16(dB + s * ST1, srcB + s * 64);
        CP16(dB + s * ST1 + 16, srcB + s * 64 + 16);
        CP_COMMIT();
    }

    int warp = tid >> 5, lane = tid & 31;
    int wm = warp & 1, wn = warp >> 1;           // 2 m x 4 n warps
    int sub = lane >> 2, q4 = (lane & 3) * 4;
    int accg[2][2][4], accu[2][2][4];
#pragma unroll
    for (int mt = 0; mt < 2; ++mt)
#pragma unroll
        for (int n8 = 0; n8 < 2; ++n8)
#pragma unroll
            for (int r = 0; r < 4; ++r) { accg[mt][n8][r] = 0; accu[mt][n8][r] = 0; }

    for (int ks = 0; ks < NS1; ++ks) {
        CP_WAIT1();
        __syncthreads();
        const char* As = smem + (ks % 3) * ST1;
        const char* Bs = As + 5120;
#pragma unroll
        for (int kk = 0; kk < 64; kk += 32) {
            uint32_t a[2][4];
#pragma unroll
            for (int mt = 0; mt < 2; ++mt) {
                const char* ar = As + (wm * 32 + mt * 16 + sub) * PAD + kk + q4;
                a[mt][0] = *(const uint32_t*)(ar);
                a[mt][1] = *(const uint32_t*)(ar + 8 * PAD);
                a[mt][2] = *(const uint32_t*)(ar + 16);
                a[mt][3] = *(const uint32_t*)(ar + 8 * PAD + 16);
            }
#pragma unroll
            for (int n8 = 0; n8 < 2; ++n8) {
                const char* bg = Bs + (wn * 16 + n8 * 8 + sub) * PAD + kk + q4;
                uint32_t g0 = *(const uint32_t*)(bg);
                uint32_t g1 = *(const uint32_t*)(bg + 16);
                uint32_t u0 = *(const uint32_t*)(bg + 64 * PAD);
                uint32_t u1 = *(const uint32_t*)(bg + 64 * PAD + 16);
#pragma unroll
                for (int mt = 0; mt < 2; ++mt) {
                    mma_s8(accg[mt][n8], a[mt][0], a[mt][1], a[mt][2], a[mt][3], g0, g1);
                    mma_s8(accu[mt][n8], a[mt][0], a[mt][1], a[mt][2], a[mt][3], u0, u1);
                }
            }
        }
        if (ks + 2 < NS1) {
            int s = (ks + 2) % 3;
            int kb = (ks + 2) * 64;
            CP16(dA + s * ST1, srcA + kb);
            CP16(dB + s * ST1, srcB + kb);
            CP16(dB + s * ST1 + 16, srcB + kb + 16);
        }
        CP_COMMIT();
    }

    // epilogue: silu(g)*u -> g_act
    const float* s13 = s13_all + (size_t)e * TWOI + z * 64;
#pragma unroll
    for (int mt = 0; mt < 2; ++mt) {
#pragma unroll
        for (int n8 = 0; n8 < 2; ++n8) {
            int col = wn * 16 + n8 * 8 + (lane & 3) * 2;
            float sg0 = s13[col], sg1 = s13[col + 1];
            float su0 = s13[col + I_], su1 = s13[col + I_ + 1];
#pragma unroll
            for (int h2 = 0; h2 < 2; ++h2) {
                int row = wm * 32 + mt * 16 + sub + h2 * 8;
                if (row < nt) {
                    float si = sin_s[row];
                    float g0 = (float)accg[mt][n8][h2 * 2 + 0] * si * sg0;
                    float g1 = (float)accg[mt][n8][h2 * 2 + 1] * si * sg1;
                    float u0 = (float)accu[mt][n8][h2 * 2 + 0] * si * su0;
                    float u1 = (float)accu[mt][n8][h2 * 2 + 1] * si * su1;
                    float a0 = g0 * __fdiv_rn(1.f, 1.f + expf(-g0)) * u0;
                    float a1 = g1 * __fdiv_rn(1.f, 1.f + expf(-g1)) * u1;
                    *(float2*)(g_act + (size_t)dst_s[row] * I_ + z * 64 + col) =
                        make_float2(a0, a1);
                }
            }
        }
    }
}

// ---------------- requant ----------------
__global__ __launch_bounds__(128) void requant_kernel() {
    int dst = blockIdx.x;
    const float* a = g_act + (size_t)dst * I_;
    int tid = threadIdx.x;
    float m = 0.f;
    for (int i = tid; i < I_; i += 128) m = fmaxf(m, fabsf(a[i]));
    __shared__ float red[4];
#pragma unroll
    for (int off = 16; off; off >>= 1) m = fmaxf(m, __shfl_down_sync(0xffffffffu, m, off));
    if ((tid & 31) == 0) red[tid >> 5] = m;
    __syncthreads();
    float mm = fmaxf(fmaxf(red[0], red[1]), fmaxf(red[2], red[3]));
    float sa = fmaxf(__fdiv_rn(mm, 127.f), 1e-8f);
    if (tid == 0) g_sa[dst] = sa;
    int8_t* q = g_qact + (size_t)dst * I_;
    for (int i = tid; i < I_; i += 128) {
        float v = fminf(fmaxf(rintf(__fdiv_rn(a[i], sa)), -127.f), 127.f);
        q[i] = (int8_t)v;
    }
}

// ---------------- zero output ----------------
__global__ __launch_bounds__(256) void zero_out_kernel(float* __restrict__ out) {
    size_t idx = (size_t)blockIdx.x * 256 + threadIdx.x;
    ((float4*)out)[idx] = make_float4(0.f, 0.f, 0.f, 0.f);
}

// ===========================================================================
// GEMM2: M=64 tokens x 128 h-cols, K=1408. grid (64, E, 16), 256 threads.
// Epilogue: atomicAdd gated values directly into out (2 adds per element).
// ===========================================================================
#define ST2    15360
#define G2_META (3 * ST2)
#define G2_SMEM (G2_META + 1024)
#define NS2    22

__global__ __launch_bounds__(256, 3) void gemm2_mma(const float* __restrict__ s2_all,
                                                    float* __restrict__ out) {
    int e = blockIdx.y;
    int cnt = g_cnt[e];
    int m0 = blockIdx.x * 64;
    if (m0 >= cnt) return;
    int nt = min(64, cnt - m0);
    int z = blockIdx.z;           // 128 h-cols

    extern __shared__ char smem[];
    uint32_t sb = smem_u32(smem);
    int* dst_s = (int*)(smem + G2_META);
    float* sc_s = (float*)(smem + G2_META + 256);   // sa * gate
    int tid = threadIdx.x;

    if (tid < 64) {
        int packed; float gv;
        if (tid < nt) { packed = g_tok[e][m0 + tid]; gv = g_gate_arr[e][m0 + tid]; }
        else          { packed = g_tok[e][m0];       gv = 0.f; }
        dst_s[tid] = packed;
        sc_s[tid] = gv * g_sa[packed];
    }
    __syncthreads();

    const int8_t* w2 = g_w2 + (size_t)e * H_ * I_;
    int rA = tid >> 2, cA = (tid & 3) * 16;
    const int8_t* srcA = g_qact + (size_t)dst_s[rA] * I_ + cA;
    int rB = tid >> 1, cB = (tid & 1) * 32;
    const int8_t* srcB = w2 + (size_t)(z * 128 + rB) * I_ + cB;
    uint32_t dA = sb + rA * PAD + cA;
    uint32_t dB = sb + 5120 + rB * PAD + cB;

#pragma unroll
    for (int s = 0; s < 2; ++s) {
        CP16(dA + s * ST2, srcA + s * 64);
        CP16(dB + s * ST2, srcB + s * 64);
        CP16(dB + s * ST2 + 16, srcB + s * 64 + 16);
        CP_COMMIT();
    }

    int warp = tid >> 5, lane = tid & 31;
    int wm = warp & 1, wn = warp >> 1;
    int sub = lane >> 2, q4 = (lane & 3) * 4;
    int acc[2][4][4];
#pragma unroll
    for (int mt = 0; mt < 2; ++mt)
#pragma unroll
        for (int n8 = 0; n8 < 4; ++n8)
#pragma unroll
            for (int r = 0; r < 4; ++r) acc[mt][n8][r] = 0;

    for (int ks = 0; ks < NS2; ++ks) {
        CP_WAIT1();
        __syncthreads();
        const char* As = smem + (ks % 3) * ST2;
        const char* Bs = As + 5120;
#pragma unroll
        for (int kk = 0; kk < 64; kk += 32) {
            uint32_t a[2][4];
#pragma unroll
            for (int mt = 0; mt < 2; ++mt) {
                const char* ar = As + (wm * 32 + mt * 16 + sub) * PAD + kk + q4;
                a[mt][0] = *(const uint32_t*)(ar);
                a[mt][1] = *(const uint32_t*)(ar + 8 * PAD);
                a[mt][2] = *(const uint32_t*)(ar + 16);
                a[mt][3] = *(const uint32_t*)(ar + 8 * PAD + 16);
            }
#pragma unroll
            for (int n8 = 0; n8 < 4; ++n8) {
                const char* br = Bs + (wn * 32 + n8 * 8 + sub) * PAD + kk + q4;
                uint32_t b0 = *(const uint32_t*)(br);
                uint32_t b1 = *(const uint32_t*)(br + 16);
#pragma unroll
                for (int mt = 0; mt < 2; ++mt)
                    mma_s8(acc[mt][n8], a[mt][0], a[mt][1], a[mt][2], a[mt][3], b0, b1);
            }
        }
        if (ks + 2 < NS2) {
            int s = (ks + 2) % 3;
            int kb = (ks + 2) * 64;
            CP16(dA + s * ST2, srcA + kb);
            CP16(dB + s * ST2, srcB + kb);
            CP16(dB + s * ST2 + 16, srcB + kb + 16);
        }
        CP_COMMIT();
    }

    const float* s2w = s2_all + (size_t)e * H_ + z * 128;
#pragma unroll
    for (int mt = 0; mt < 2; ++mt) {
#pragma unroll
        for (int n8 = 0; n8 < 4; ++n8) {
            int col = wn * 32 + n8 * 8 + (lane & 3) * 2;
            float w0 = s2w[col], w1 = s2w[col + 1];
#pragma unroll
            for (int h2 = 0; h2 < 2; ++h2) {
                int row = wm * 32 + mt * 16 + sub + h2 * 8;
                if (row < nt) {
                    float sc = sc_s[row];
                    int t = dst_s[row] >> 1;
                    float* orow = out + (size_t)t * H_ + z * 128 + col;
                    atomicAdd(orow, (float)acc[mt][n8][h2 * 2 + 0] * sc * w0);
                    atomicAdd(orow + 1, (float)acc[mt][n8][h2 * 2 + 1] * sc * w1);
                }
            }
        }
    }
}

// ---------------------------------------------------------------------------
extern "C" void kernel_launch(void* const* d_in, const int* in_sizes, int n_in,
                              void* d_out, int out_size) {
    const float* hid = nullptr;
    const float* gw = nullptr;
    const void* w13raw = nullptr;
    const float* s13 = nullptr;
    const void* w2raw = nullptr;
    const float* s2 = nullptr;
    for (int i = 0; i < n_in; ++i) {
        long long s = in_sizes[i];
        if (s == 8388608LL || s == 33554432LL) hid = (const float*)d_in[i];
        else if (s == 46137344LL || s == 184549376LL) w13raw = d_in[i];
        else if (s == 22528LL || s == 90112LL) s13 = (const float*)d_in[i];
        else if (s == 23068672LL || s == 92274688LL) w2raw = d_in[i];
        else if (s == 16384LL || s == 65536LL) {
            if (!gw) gw = (const float*)d_in[i];
            else s2 = (const float*)d_in[i];
        }
    }
    if (n_in >= 6) {
        if (!hid)    hid = (const float*)d_in[0];
        if (!gw)     gw = (const float*)d_in[1];
        if (!w13raw) w13raw = d_in[2];
        if (!s13)    s13 = (const float*)d_in[3];
        if (!w2raw)  w2raw = d_in[4];
        if (!s2)     s2 = (const float*)d_in[5];
    }
    float* out = (float*)d_out;

    cudaFuncSetAttribute(gemm1_mma, cudaFuncAttributeMaxDynamicSharedMemorySize, G1_SMEM);
    cudaFuncSetAttribute(gemm2_mma, cudaFuncAttributeMaxDynamicSharedMemorySize, G2_SMEM);

    convert_w13_kernel<<<8192, 256>>>(w13raw);            // 1
    convert_w2_kernel<<<8192, 256>>>(w2raw);              // 2
    gatequant_kernel<<<T_, 256>>>(hid, gw);               // 3
    dim3 g1(64, E_, 22);
    gemm1_mma<<<g1, 256, G1_SMEM>>>(s13);                 // 4 (profiled slot)
    requant_kernel<<<T_ * 2, 128>>>();                    // 5
    zero_out_kernel<<<(T_ * H_) / 1024, 256>>>(out);      // 6
    dim3 g2(64, E_, 16);
    gemm2_mma<<<g2, 256, G2_SMEM>>>(s2, out);             // 7
}

// round 10
// speedup vs baseline: 4.6699x; 1.2977x over previous
#include <cuda_runtime.h>
#include <cstdint>
#include <math.h>

#define T_    4096
#define H_    2048
#define I_    1408
#define E_    8
#define TWOI  2816

// ---------------- scratch ----------------
__device__ int8_t g_qin[(size_t)T_ * H_];
__device__ float  g_sin[T_];
__device__ int    g_cnt[E_];
__device__ int    g_tok[E_][T_];
__device__ float  g_gate_arr[E_][T_];
__device__ int8_t g_w13[(size_t)E_ * TWOI * H_];
__device__ int8_t g_w2[(size_t)E_ * H_ * I_];
__device__ float  g_act[(size_t)T_ * 2 * I_];
__device__ int8_t g_qact[(size_t)T_ * 2 * I_];
__device__ float  g_sa[T_ * 2];

// ---------------- helpers ----------------
__device__ __forceinline__ uint32_t smem_u32(const void* p) {
    uint32_t a;
    asm("{ .reg .u64 t; cvta.to.shared.u64 t, %1; cvt.u32.u64 %0, t; }" : "=r"(a) : "l"(p));
    return a;
}
#define CP16(dst, src) asm volatile("cp.async.cg.shared.global [%0], [%1], 16;" :: "r"(dst), "l"(src))
#define CP_COMMIT()    asm volatile("cp.async.commit_group;" ::: "memory")
#define CP_WAIT1()     asm volatile("cp.async.wait_group 1;" ::: "memory")

__device__ __forceinline__ void mma_s8(int* d, uint32_t a0, uint32_t a1, uint32_t a2, uint32_t a3,
                                       uint32_t b0, uint32_t b1) {
    asm volatile("mma.sync.aligned.m16n8k32.row.col.s32.s8.s8.s32 "
                 "{%0,%1,%2,%3}, {%4,%5,%6,%7}, {%8,%9}, {%0,%1,%2,%3};"
                 : "+r"(d[0]), "+r"(d[1]), "+r"(d[2]), "+r"(d[3])
                 : "r"(a0), "r"(a1), "r"(a2), "r"(a3), "r"(b0), "r"(b1));
}

// ---------------- weight conversion ----------------
__device__ __forceinline__ char4 conv_elem(const void* __restrict__ src, int idx, int mode) {
    if (mode == 1) {
        int4 v = ((const int4*)src)[idx];
        return make_char4((signed char)v.x, (signed char)v.y, (signed char)v.z, (signed char)v.w);
    } else if (mode == 2) {
        float4 v = ((const float4*)src)[idx];
        return make_char4((signed char)(int)v.x, (signed char)(int)v.y,
                          (signed char)(int)v.z, (signed char)(int)v.w);
    }
    return ((const char4*)src)[idx];
}
__device__ __forceinline__ int block_detect_mode(const void* src) {
    int tid = threadIdx.x;
    int v = ((const int*)src)[tid];
    float f = ((const float*)src)[tid];
    int n32 = __syncthreads_count(v >= -127 && v <= 127);
    int nf = __syncthreads_count(fabsf(f) <= 127.f && rintf(f) == f);
    return (n32 >= 250) ? 1 : ((nf >= 250) ? 2 : 0);
}
#define N4_W13 ((E_ * TWOI * H_) / 4)
#define N4_W2  ((E_ * H_ * I_) / 4)

__global__ __launch_bounds__(256) void convert_w13_kernel(const void* __restrict__ src) {
    int mode = block_detect_mode(src);
    for (int idx = blockIdx.x * 256 + threadIdx.x; idx < N4_W13; idx += gridDim.x * 256)
        ((char4*)g_w13)[idx] = conv_elem(src, idx, mode);
    if (blockIdx.x == 0 && threadIdx.x < E_) g_cnt[threadIdx.x] = 0;
}
__global__ __launch_bounds__(256) void convert_w2_kernel(const void* __restrict__ src) {
    int mode = block_detect_mode(src);
    for (int idx = blockIdx.x * 256 + threadIdx.x; idx < N4_W2; idx += gridDim.x * 256)
        ((char4*)g_w2)[idx] = conv_elem(src, idx, mode);
}

// ---------------- gate + quantize ----------------
__global__ __launch_bounds__(256) void gatequant_kernel(const float* __restrict__ hid,
                                                        const float* __restrict__ gw) {
    int t = blockIdx.x;
    const float* x = hid + (size_t)t * H_;
    float part[E_];
#pragma unroll
    for (int e = 0; e < E_; ++e) part[e] = 0.f;
    float amax = 0.f;
    for (int j = threadIdx.x; j < H_; j += 256) {
        float v = x[j];
        amax = fmaxf(amax, fabsf(v));
#pragma unroll
        for (int e = 0; e < E_; ++e) part[e] = fmaf(v, gw[e * H_ + j], part[e]);
    }
#pragma unroll
    for (int off = 16; off; off >>= 1) {
        amax = fmaxf(amax, __shfl_down_sync(0xffffffffu, amax, off));
#pragma unroll
        for (int e = 0; e < E_; ++e) part[e] += __shfl_down_sync(0xffffffffu, part[e], off);
    }
    __shared__ float red[8][E_ + 1];
    __shared__ float s_sh;
    int warp = threadIdx.x >> 5, lane = threadIdx.x & 31;
    if (lane == 0) {
#pragma unroll
        for (int e = 0; e < E_; ++e) red[warp][e] = part[e];
        red[warp][E_] = amax;
    }
    __syncthreads();
    if (threadIdx.x == 0) {
        float l[E_]; float am = 0.f;
#pragma unroll
        for (int e = 0; e < E_; ++e) l[e] = 0.f;
        for (int w = 0; w < 8; ++w) {
#pragma unroll
            for (int e = 0; e < E_; ++e) l[e] += red[w][e];
            am = fmaxf(am, red[w][E_]);
        }
        float b1 = -1e30f, b2 = -1e30f; int i1 = 0, i2 = 0;
#pragma unroll
        for (int e = 0; e < E_; ++e) {
            float v = l[e];
            if (v > b1) { b2 = b1; i2 = i1; b1 = v; i1 = e; }
            else if (v > b2) { b2 = v; i2 = e; }
        }
        float e2v = expf(b2 - b1);
        float inv = __fdiv_rn(1.f, 1.f + e2v);
        float s = fmaxf(__fdiv_rn(am, 127.f), 1e-8f);
        g_sin[t] = s; s_sh = s;
        int p0 = atomicAdd(&g_cnt[i1], 1);
        g_tok[i1][p0] = t * 2 + 0; g_gate_arr[i1][p0] = inv;
        int p1 = atomicAdd(&g_cnt[i2], 1);
        g_tok[i2][p1] = t * 2 + 1; g_gate_arr[i2][p1] = e2v * inv;
    }
    __syncthreads();
    float s = s_sh;
    const float4* xv = (const float4*)x;
    char4* q = (char4*)(g_qin + (size_t)t * H_);
    for (int j = threadIdx.x; j < H_ / 4; j += 256) {
        float4 v = xv[j];
        float a = fminf(fmaxf(rintf(__fdiv_rn(v.x, s)), -127.f), 127.f);
        float b = fminf(fmaxf(rintf(__fdiv_rn(v.y, s)), -127.f), 127.f);
        float c = fminf(fmaxf(rintf(__fdiv_rn(v.z, s)), -127.f), 127.f);
        float d = fminf(fmaxf(rintf(__fdiv_rn(v.w, s)), -127.f), 127.f);
        q[j] = make_char4((signed char)a, (signed char)b, (signed char)c, (signed char)d);
    }
}

// ===========================================================================
// GEMM1 hybrid: M=64 x 64 i-cols (g+u). warps 0-3 mma (i-cols 0-31),
// warps 4-7 dp4a (i-cols 32-63). 3-stage cp.async. grid (64, E, 22).
// ===========================================================================
#define PAD    80
#define ST1    15360
#define G1_META (3 * ST1)
#define G1_SMEM (G1_META + 768)
#define NS1    32

__global__ __launch_bounds__(256, 2) void gemm1_mma(const float* __restrict__ s13_all) {
    int e = blockIdx.y;
    int cnt = g_cnt[e];
    int m0 = blockIdx.x * 64;
    if (m0 >= cnt) return;
    int nt = min(64, cnt - m0);
    int z = blockIdx.z;

    extern __shared__ char smem[];
    uint32_t sb = smem_u32(smem);
    int* dst_s = (int*)(smem + G1_META);
    float* sin_s = (float*)(smem + G1_META + 256);
    int tid = threadIdx.x;

    if (tid < 64) {
        int packed = (tid < nt) ? g_tok[e][m0 + tid] : g_tok[e][m0];
        dst_s[tid] = packed;
        sin_s[tid] = g_sin[packed >> 1];
    }
    __syncthreads();

    const int8_t* w13 = g_w13 + (size_t)e * TWOI * H_;
    int rA = tid >> 2, cA = (tid & 3) * 16;
    const int8_t* srcA = g_qin + (size_t)(dst_s[rA] >> 1) * H_ + cA;
    int rB = tid >> 1, cB = (tid & 1) * 32;
    const int8_t* srcB = (rB < 64)
        ? w13 + (size_t)(z * 64 + rB) * H_ + cB
        : w13 + (size_t)(I_ + z * 64 + (rB - 64)) * H_ + cB;
    uint32_t dA = sb + rA * PAD + cA;
    uint32_t dB = sb + 5120 + rB * PAD + cB;

#pragma unroll
    for (int s = 0; s < 2; ++s) {
        CP16(dA + s * ST1, srcA + s * 64);
        CP16(dB + s * ST1, srcB + s * 64);
        CP16(dB + s * ST1 + 16, srcB + s * 64 + 16);
        CP_COMMIT();
    }

    int warp = tid >> 5, lane = tid & 31;

    if (warp < 4) {
        // ---- mma role: i-cols [0,32) ----
        int wm = warp & 1, wn = warp >> 1;       // 2m x 2n
        int sub = lane >> 2, q4 = (lane & 3) * 4;
        int accg[2][2][4], accu[2][2][4];
#pragma unroll
        for (int mt = 0; mt < 2; ++mt)
#pragma unroll
            for (int n8 = 0; n8 < 2; ++n8)
#pragma unroll
                for (int r = 0; r < 4; ++r) { accg[mt][n8][r] = 0; accu[mt][n8][r] = 0; }

        for (int ks = 0; ks < NS1; ++ks) {
            CP_WAIT1();
            __syncthreads();
            const char* As = smem + (ks % 3) * ST1;
            const char* Bs = As + 5120;
#pragma unroll
            for (int kk = 0; kk < 64; kk += 32) {
                uint32_t a[2][4];
#pragma unroll
                for (int mt = 0; mt < 2; ++mt) {
                    const char* ar = As + (wm * 32 + mt * 16 + sub) * PAD + kk + q4;
                    a[mt][0] = *(const uint32_t*)(ar);
                    a[mt][1] = *(const uint32_t*)(ar + 8 * PAD);
                    a[mt][2] = *(const uint32_t*)(ar + 16);
                    a[mt][3] = *(const uint32_t*)(ar + 8 * PAD + 16);
                }
#pragma unroll
                for (int n8 = 0; n8 < 2; ++n8) {
                    const char* bg = Bs + (wn * 16 + n8 * 8 + sub) * PAD + kk + q4;
                    uint32_t g0 = *(const uint32_t*)(bg);
                    uint32_t g1 = *(const uint32_t*)(bg + 16);
                    uint32_t u0 = *(const uint32_t*)(bg + 64 * PAD);
                    uint32_t u1 = *(const uint32_t*)(bg + 64 * PAD + 16);
#pragma unroll
                    for (int mt = 0; mt < 2; ++mt) {
                        mma_s8(accg[mt][n8], a[mt][0], a[mt][1], a[mt][2], a[mt][3], g0, g1);
                        mma_s8(accu[mt][n8], a[mt][0], a[mt][1], a[mt][2], a[mt][3], u0, u1);
                    }
                }
            }
            if (ks + 2 < NS1) {
                int s = (ks + 2) % 3;
                int kb = (ks + 2) * 64;
                CP16(dA + s * ST1, srcA + kb);
                CP16(dB + s * ST1, srcB + kb);
                CP16(dB + s * ST1 + 16, srcB + kb + 16);
            }
            CP_COMMIT();
        }

        const float* s13 = s13_all + (size_t)e * TWOI + z * 64;
#pragma unroll
        for (int mt = 0; mt < 2; ++mt) {
#pragma unroll
            for (int n8 = 0; n8 < 2; ++n8) {
                int col = wn * 16 + n8 * 8 + (lane & 3) * 2;
                float sg0 = s13[col], sg1 = s13[col + 1];
                float su0 = s13[col + I_], su1 = s13[col + I_ + 1];
#pragma unroll
                for (int h2 = 0; h2 < 2; ++h2) {
                    int row = wm * 32 + mt * 16 + sub + h2 * 8;
                    if (row < nt) {
                        float si = sin_s[row];
                        float g0 = (float)accg[mt][n8][h2 * 2 + 0] * si * sg0;
                        float g1 = (float)accg[mt][n8][h2 * 2 + 1] * si * sg1;
                        float u0 = (float)accu[mt][n8][h2 * 2 + 0] * si * su0;
                        float u1 = (float)accu[mt][n8][h2 * 2 + 1] * si * su1;
                        float a0 = g0 * __fdiv_rn(1.f, 1.f + expf(-g0)) * u0;
                        float a1 = g1 * __fdiv_rn(1.f, 1.f + expf(-g1)) * u1;
                        *(float2*)(g_act + (size_t)dst_s[row] * I_ + z * 64 + col) =
                            make_float2(a0, a1);
                    }
                }
            }
        }
    } else {
        // ---- dp4a role: i-cols [32,64) ----
        int col = 32 + (warp - 4) * 8 + (lane & 7);
        int rg = lane >> 3;                       // 0..3, rows rg*16..+16
        int accg[16], accu[16];
#pragma unroll
        for (int r = 0; r < 16; ++r) { accg[r] = 0; accu[r] = 0; }

        for (int ks = 0; ks < NS1; ++ks) {
            CP_WAIT1();
            __syncthreads();
            const char* As = smem + (ks % 3) * ST1;
            const char* Bs = As + 5120;
#pragma unroll
            for (int j = 0; j < 4; ++j) {
                int kk4 = ((rg + j) & 3) * 16;    // rotate to avoid A bank conflicts
                int4 bg = *(const int4*)(Bs + col * PAD + kk4);
                int4 bu = *(const int4*)(Bs + (64 + col) * PAD + kk4);
#pragma unroll
                for (int r = 0; r < 16; ++r) {
                    int4 av = *(const int4*)(As + (rg * 16 + r) * PAD + kk4);
                    accg[r] = __dp4a(av.x, bg.x, accg[r]);
                    accg[r] = __dp4a(av.y, bg.y, accg[r]);
                    accg[r] = __dp4a(av.z, bg.z, accg[r]);
                    accg[r] = __dp4a(av.w, bg.w, accg[r]);
                    accu[r] = __dp4a(av.x, bu.x, accu[r]);
                    accu[r] = __dp4a(av.y, bu.y, accu[r]);
                    accu[r] = __dp4a(av.z, bu.z, accu[r]);
                    accu[r] = __dp4a(av.w, bu.w, accu[r]);
                }
            }
            if (ks + 2 < NS1) {
                int s = (ks + 2) % 3;
                int kb = (ks + 2) * 64;
                CP16(dA + s * ST1, srcA + kb);
                CP16(dB + s * ST1, srcB + kb);
                CP16(dB + s * ST1 + 16, srcB + kb + 16);
            }
            CP_COMMIT();
        }

        const float* s13 = s13_all + (size_t)e * TWOI + z * 64;
        float sg = s13[col], su = s13[col + I_];
#pragma unroll
        for (int r = 0; r < 16; ++r) {
            int row = rg * 16 + r;
            if (row < nt) {
                float si = sin_s[row];
                float g = (float)accg[r] * si * sg;
                float u = (float)accu[r] * si * su;
                g_act[(size_t)dst_s[row] * I_ + z * 64 + col] =
                    g * __fdiv_rn(1.f, 1.f + expf(-g)) * u;
            }
        }
    }
}

// ---------------- requant ----------------
__global__ __launch_bounds__(128) void requant_kernel() {
    int dst = blockIdx.x;
    const float* a = g_act + (size_t)dst * I_;
    int tid = threadIdx.x;
    float m = 0.f;
    for (int i = tid; i < I_; i += 128) m = fmaxf(m, fabsf(a[i]));
    __shared__ float red[4];
#pragma unroll
    for (int off = 16; off; off >>= 1) m = fmaxf(m, __shfl_down_sync(0xffffffffu, m, off));
    if ((tid & 31) == 0) red[tid >> 5] = m;
    __syncthreads();
    float mm = fmaxf(fmaxf(red[0], red[1]), fmaxf(red[2], red[3]));
    float sa = fmaxf(__fdiv_rn(mm, 127.f), 1e-8f);
    if (tid == 0) g_sa[dst] = sa;
    int8_t* q = g_qact + (size_t)dst * I_;
    for (int i = tid; i < I_; i += 128) {
        float v = fminf(fmaxf(rintf(__fdiv_rn(a[i], sa)), -127.f), 127.f);
        q[i] = (int8_t)v;
    }
}

// ---------------- zero output ----------------
__global__ __launch_bounds__(256) void zero_out_kernel(float* __restrict__ out) {
    size_t idx = (size_t)blockIdx.x * 256 + threadIdx.x;
    ((float4*)out)[idx] = make_float4(0.f, 0.f, 0.f, 0.f);
}

// ===========================================================================
// GEMM2 hybrid: M=64 x 128 h-cols. warps 0-3 mma (cols 0-63),
// warps 4-7 dp4a (cols 64-127). grid (64, E, 16). atomicAdd into out.
// ===========================================================================
#define ST2    15360
#define G2_META (3 * ST2)
#define G2_SMEM (G2_META + 1024)
#define NS2    22

__global__ __launch_bounds__(256, 2) void gemm2_mma(const float* __restrict__ s2_all,
                                                    float* __restrict__ out) {
    int e = blockIdx.y;
    int cnt = g_cnt[e];
    int m0 = blockIdx.x * 64;
    if (m0 >= cnt) return;
    int nt = min(64, cnt - m0);
    int z = blockIdx.z;

    extern __shared__ char smem[];
    uint32_t sb = smem_u32(smem);
    int* dst_s = (int*)(smem + G2_META);
    float* sc_s = (float*)(smem + G2_META + 256);
    int tid = threadIdx.x;

    if (tid < 64) {
        int packed; float gv;
        if (tid < nt) { packed = g_tok[e][m0 + tid]; gv = g_gate_arr[e][m0 + tid]; }
        else          { packed = g_tok[e][m0];       gv = 0.f; }
        dst_s[tid] = packed;
        sc_s[tid] = gv * g_sa[packed];
    }
    __syncthreads();

    const int8_t* w2 = g_w2 + (size_t)e * H_ * I_;
    int rA = tid >> 2, cA = (tid & 3) * 16;
    const int8_t* srcA = g_qact + (size_t)dst_s[rA] * I_ + cA;
    int rB = tid >> 1, cB = (tid & 1) * 32;
    const int8_t* srcB = w2 + (size_t)(z * 128 + rB) * I_ + cB;
    uint32_t dA = sb + rA * PAD + cA;
    uint32_t dB = sb + 5120 + rB * PAD + cB;

#pragma unroll
    for (int s = 0; s < 2; ++s) {
        CP16(dA + s * ST2, srcA + s * 64);
        CP16(dB + s * ST2, srcB + s * 64);
        CP16(dB + s * ST2 + 16, srcB + s * 64 + 16);
        CP_COMMIT();
    }

    int warp = tid >> 5, lane = tid & 31;

    if (warp < 4) {
        // ---- mma role: h-cols [0,64) ----
        int wm = warp & 1, wn = warp >> 1;
        int sub = lane >> 2, q4 = (lane & 3) * 4;
        int acc[2][4][4];
#pragma unroll
        for (int mt = 0; mt < 2; ++mt)
#pragma unroll
            for (int n8 = 0; n8 < 4; ++n8)
#pragma unroll
                for (int r = 0; r < 4; ++r) acc[mt][n8][r] = 0;

        for (int ks = 0; ks < NS2; ++ks) {
            CP_WAIT1();
            __syncthreads();
            const char* As = smem + (ks % 3) * ST2;
            const char* Bs = As + 5120;
#pragma unroll
            for (int kk = 0; kk < 64; kk += 32) {
                uint32_t a[2][4];
#pragma unroll
                for (int mt = 0; mt < 2; ++mt) {
                    const char* ar = As + (wm * 32 + mt * 16 + sub) * PAD + kk + q4;
                    a[mt][0] = *(const uint32_t*)(ar);
                    a[mt][1] = *(const uint32_t*)(ar + 8 * PAD);
                    a[mt][2] = *(const uint32_t*)(ar + 16);
                    a[mt][3] = *(const uint32_t*)(ar + 8 * PAD + 16);
                }
#pragma unroll
                for (int n8 = 0; n8 < 4; ++n8) {
                    const char* br = Bs + (wn * 32 + n8 * 8 + sub) * PAD + kk + q4;
                    uint32_t b0 = *(const uint32_t*)(br);
                    uint32_t b1 = *(const uint32_t*)(br + 16);
#pragma unroll
                    for (int mt = 0; mt < 2; ++mt)
                        mma_s8(acc[mt][n8], a[mt][0], a[mt][1], a[mt][2], a[mt][3], b0, b1);
                }
            }
            if (ks + 2 < NS2) {
                int s = (ks + 2) % 3;
                int kb = (ks + 2) * 64;
                CP16(dA + s * ST2, srcA + kb);
                CP16(dB + s * ST2, srcB + kb);
                CP16(dB + s * ST2 + 16, srcB + kb + 16);
            }
            CP_COMMIT();
        }

        const float* s2w = s2_all + (size_t)e * H_ + z * 128;
#pragma unroll
        for (int mt = 0; mt < 2; ++mt) {
#pragma unroll
            for (int n8 = 0; n8 < 4; ++n8) {
                int col = wn * 32 + n8 * 8 + (lane & 3) * 2;
                float w0 = s2w[col], w1 = s2w[col + 1];
#pragma unroll
                for (int h2 = 0; h2 < 2; ++h2) {
                    int row = wm * 32 + mt * 16 + sub + h2 * 8;
                    if (row < nt) {
                        float sc = sc_s[row];
                        int t = dst_s[row] >> 1;
                        float* orow = out + (size_t)t * H_ + z * 128 + col;
                        atomicAdd(orow, (float)acc[mt][n8][h2 * 2 + 0] * sc * w0);
                        atomicAdd(orow + 1, (float)acc[mt][n8][h2 * 2 + 1] * sc * w1);
                    }
                }
            }
        }
    } else {
        // ---- dp4a role: h-cols [64,128) ----
        int col = 64 + (warp - 4) * 16 + (lane & 15);
        int rg = lane >> 4;                       // 0..1, rows rg*32..+32
        int acc[32];
#pragma unroll
        for (int r = 0; r < 32; ++r) acc[r] = 0;

        for (int ks = 0; ks < NS2; ++ks) {
            CP_WAIT1();
            __syncthreads();
            const char* As = smem + (ks % 3) * ST2;
            const char* Bs = As + 5120;
#pragma unroll
            for (int j = 0; j < 4; ++j) {
                int kk4 = ((rg * 2 + j) & 3) * 16;
                int4 bv = *(const int4*)(Bs + col * PAD + kk4);
#pragma unroll
                for (int r = 0; r < 32; ++r) {
                    int4 av = *(const int4*)(As + (rg * 32 + r) * PAD + kk4);
                    acc[r] = __dp4a(av.x, bv.x, acc[r]);
                    acc[r] = __dp4a(av.y, bv.y, acc[r]);
                    acc[r] = __dp4a(av.z, bv.z, acc[r]);
                    acc[r] = __dp4a(av.w, bv.w, acc[r]);
                }
            }
            if (ks + 2 < NS2) {
                int s = (ks + 2) % 3;
                int kb = (ks + 2) * 64;
                CP16(dA + s * ST2, srcA + kb);
                CP16(dB + s * ST2, srcB + kb);
                CP16(dB + s * ST2 + 16, srcB + kb + 16);
            }
            CP_COMMIT();
        }

        const float* s2w = s2_all + (size_t)e * H_ + z * 128;
        float w0 = s2w[col];
#pragma unroll
        for (int r = 0; r < 32; ++r) {
            int row = rg * 32 + r;
            if (row < nt) {
                float sc = sc_s[row];
                int t = dst_s[row] >> 1;
                atomicAdd(out + (size_t)t * H_ + z * 128 + col,
                          (float)acc[r] * sc * w0);
            }
        }
    }
}

// ---------------------------------------------------------------------------
extern "C" void kernel_launch(void* const* d_in, const int* in_sizes, int n_in,
                              void* d_out, int out_size) {
    const float* hid = nullptr;
    const float* gw = nullptr;
    const void* w13raw = nullptr;
    const float* s13 = nullptr;
    const void* w2raw = nullptr;
    const float* s2 = nullptr;
    for (int i = 0; i < n_in; ++i) {
        long long s = in_sizes[i];
        if (s == 8388608LL || s == 33554432LL) hid = (const float*)d_in[i];
        else if (s == 46137344LL || s == 184549376LL) w13raw = d_in[i];
        else if (s == 22528LL || s == 90112LL) s13 = (const float*)d_in[i];
        else if (s == 23068672LL || s == 92274688LL) w2raw = d_in[i];
        else if (s == 16384LL || s == 65536LL) {
            if (!gw) gw = (const float*)d_in[i];
            else s2 = (const float*)d_in[i];
        }
    }
    if (n_in >= 6) {
        if (!hid)    hid = (const float*)d_in[0];
        if (!gw)     gw = (const float*)d_in[1];
        if (!w13raw) w13raw = d_in[2];
        if (!s13)    s13 = (const float*)d_in[3];
        if (!w2raw)  w2raw = d_in[4];
        if (!s2)     s2 = (const float*)d_in[5];
    }
    float* out = (float*)d_out;

    cudaFuncSetAttribute(gemm1_mma, cudaFuncAttributeMaxDynamicSharedMemorySize, G1_SMEM);
    cudaFuncSetAttribute(gemm2_mma, cudaFuncAttributeMaxDynamicSharedMemorySize, G2_SMEM);

    convert_w13_kernel<<<8192, 256>>>(w13raw);            // 1
    convert_w2_kernel<<<8192, 256>>>(w2raw);              // 2
    gatequant_kernel<<<T_, 256>>>(hid, gw);               // 3
    dim3 g1(64, E_, 22);
    gemm1_mma<<<g1, 256, G1_SMEM>>>(s13);                 // 4 (profiled slot)
    requant_kernel<<<T_ * 2, 128>>>();                    // 5
    zero_out_kernel<<<(T_ * H_) / 1024, 256>>>(out);      // 6
    dim3 g2(64, E_, 16);
    gemm2_mma<<<g2, 256, G2_SMEM>>>(s2, out);             // 7
}